// round 13
// baseline (speedup 1.0000x reference)
#include <cuda_runtime.h>
#include <cuda_bf16.h>
#include <cuda_fp16.h>
#include <math.h>
#include <stdint.h>

// Graph_Critic_Model on GB300 (plain sm_103 target: no tcgen05; HMMA mma.sync path).
// Self-loop-only graph => GCNConv collapses to dense GEMM:
//   X  = relu(obs @ W1 + b1)   [131072,256]
//   Xg = relu(X @ Wg + bg)     [131072,256]
//   global LN over all elements; sigmoid-gated pooling; tiny MLP; broadcast.
// Precision (R12-proven): fp16 weights+activations, fp32 accumulate; Xg bf16.
// R13: A tile aliases X region (A dead after GEMM1) -> freed 35KB buys a 3rd
//      weight buffer; stage chunk g+2 while computing g (2-iteration slack).

#define N_NODES 131072
#define F_DIM   128
#define HID     256
#define POL     512
#define LN_EPS  1e-5f

#define BM      128         // rows per CTA
#define THREADS 512         // 16 warps: wm = wid&3 (32 rows), wn = wid>>2 (64 cols)

// smem strides (fp16 elems); pitches 272/144/528 bytes -> conflict-free ldmatrix
#define SA_STR 136
#define SB_STR 72           // 64-k weight chunk rows (144B pitch)
#define SX_STR 264

// smem byte offsets — A aliases the start of X (A: 34816 <= X: 67584)
#define OFF_A    0
#define OFF_X    0
#define OFF_B0   67584                // 36864 each buffer
#define OFF_B1   104448
#define OFF_B2   141312
#define OFF_BB1  178176               // 1024 (b1 floats)
#define OFF_BBG  179200               // 1024 (bg floats)
#define OFF_RED  180224               // 4096
#define SMEM_TOTAL 184320

// ---------------- helpers ----------------
__device__ __forceinline__ uint32_t smem_u32(const void* p) {
    uint32_t a;
    asm("{ .reg .u64 t; cvta.to.shared.u64 t, %1; cvt.u32.u64 %0, t; }" : "=r"(a) : "l"(p));
    return a;
}
__device__ __forceinline__ uint32_t pack_h2(float lo, float hi) {
    __half2 h = __floats2half2_rn(lo, hi);
    return *reinterpret_cast<uint32_t*>(&h);
}
__device__ __forceinline__ uint32_t pack_bf2(float lo, float hi) {
    __nv_bfloat162 h = __floats2bfloat162_rn(lo, hi);
    return *reinterpret_cast<uint32_t*>(&h);
}
__device__ __forceinline__ void ldsm_x4(uint32_t& r0, uint32_t& r1, uint32_t& r2, uint32_t& r3,
                                        uint32_t addr) {
    asm volatile("ldmatrix.sync.aligned.m8n8.x4.shared.b16 {%0,%1,%2,%3}, [%4];"
                 : "=r"(r0), "=r"(r1), "=r"(r2), "=r"(r3) : "r"(addr));
}
__device__ __forceinline__ void mma_f16(float* d, const uint32_t* a, uint32_t b0, uint32_t b1) {
    asm volatile("mma.sync.aligned.m16n8k16.row.col.f32.f16.f16.f32 "
                 "{%0,%1,%2,%3}, {%4,%5,%6,%7}, {%8,%9}, {%0,%1,%2,%3};"
                 : "+f"(d[0]), "+f"(d[1]), "+f"(d[2]), "+f"(d[3])
                 : "r"(a[0]), "r"(a[1]), "r"(a[2]), "r"(a[3]), "r"(b0), "r"(b1));
}
__device__ __forceinline__ void cp16(uint32_t dst, const void* src) {
    asm volatile("cp.async.cg.shared.global [%0], [%1], 16;" :: "r"(dst), "l"(src));
}
#define CP_COMMIT() asm volatile("cp.async.commit_group;" ::: "memory")
#define CP_WAIT(n)  asm volatile("cp.async.wait_group %0;" :: "n"(n) : "memory")

// ---------------- device scratch ----------------
__device__ __align__(16) __nv_bfloat16 g_Xg[(size_t)N_NODES * HID];   // 64MB
__device__ __align__(16) __half g_W1T[HID * F_DIM];                   // [n][k] fp16
__device__ __align__(16) __half g_WgT[HID * HID];                     // [n][k] fp16
__device__ double g_sum_d, g_sumsq_d;
__device__ double g_pooled[HID];
__device__ float  g_h1[HID];
__device__ float  g_h2[POL];
__device__ float  g_h3[POL];

// ---------------------------------------------------------------------------
__global__ void prep_zero_kernel() {
    int t = threadIdx.x;
    if (t == 0) { g_sum_d = 0.0; g_sumsq_d = 0.0; }
    if (t < HID) g_pooled[t] = 0.0;
}
__global__ void prep_w_kernel(const float* __restrict__ W1, const float* __restrict__ Wg) {
    int i = blockIdx.x * blockDim.x + threadIdx.x;
    if (i < HID * F_DIM) {                        // W1 is [128 k][256 n]
        int n = i >> 7, k = i & 127;
        g_W1T[i] = __float2half_rn(W1[k * HID + n]);
    }
    int j = i - HID * F_DIM;
    if (j >= 0 && j < HID * HID) {                // Wg is [256 k][256 n]
        int n = j >> 8, k = j & 255;
        g_WgT[j] = __float2half_rn(Wg[k * HID + n]);
    }
}

// ---------------------------------------------------------------------------
// stage chunk g (global index 0..5) into its rotating buffer via cp.async.
// g 0..1 -> W1T chunks 0..1; g 2..5 -> WgT chunks 0..3.
__device__ __forceinline__ void stage_g(uint32_t sb, int tid, int g) {
    const uint32_t offs[3] = {OFF_B0, OFF_B1, OFF_B2};
    uint32_t off = offs[g % 3];
    const __half* src = (g < 2) ? g_W1T : g_WgT;
    int kpitch = (g < 2) ? F_DIM : HID;
    int c = (g < 2) ? g : (g - 2);
    #pragma unroll
    for (int i = tid; i < 2048; i += THREADS) {
        int n = i >> 3, q = i & 7;                // 8 x 16B per 64-k row
        uint32_t d = (uint32_t)(n * (SB_STR * 2) + q * 16);
        const char* s = (const char*)(src + (size_t)n * kpitch + c * 64) + q * 16;
        cp16(sb + off + d, s);
    }
    CP_COMMIT();
}

// ---------------------------------------------------------------------------
// Fused GEMM1+GEMM2 per 128-row tile; HMMA fp16, fp32 accumulate.
// 16 warps x (32x64) tiles; 64-k chunks, TRIPLE-buffered (stage g+2 during g).
__global__ __launch_bounds__(THREADS, 1)
void fused_gemm_kernel(const float* __restrict__ obs,
                       const float* __restrict__ b1, const float* __restrict__ bg)
{
    extern __shared__ char smem[];
    const uint32_t sb = smem_u32(smem);
    const int tid  = threadIdx.x;
    const int lane = tid & 31;
    const int wid  = tid >> 5;
    const int wm   = wid & 3;        // row group: 32 rows
    const int wn   = wid >> 2;       // col group: 64 cols
    const size_t row0 = (size_t)blockIdx.x * BM;

    const uint32_t b_offs[3] = {OFF_B0, OFF_B1, OFF_B2};

    // prologue: stage chunks 0 and 1 (overlap the A staging below)
    stage_g(sb, tid, 0);
    stage_g(sb, tid, 1);

    float* b1s = (float*)(smem + OFF_BB1);
    float* bgs = (float*)(smem + OFF_BBG);
    if (tid < 256) { b1s[tid] = b1[tid]; bgs[tid] = bg[tid]; }

    // ---- stage obs [128 x 128] fp32 -> fp16 into sA (aliases X region) ----
    const float4* obs4 = reinterpret_cast<const float4*>(obs + row0 * F_DIM);
    #pragma unroll
    for (int i = tid; i < 128 * 32; i += THREADS) {
        int r = i >> 5, c4 = i & 31;
        float4 v = obs4[i];
        uint2 p = make_uint2(pack_h2(v.x, v.y), pack_h2(v.z, v.w));
        *(uint2*)(smem + OFF_A + r * (SA_STR * 2) + c4 * 8) = p;
    }

    float acc[16][4];
    #pragma unroll
    for (int t = 0; t < 16; ++t)
        #pragma unroll
        for (int j = 0; j < 4; ++j) acc[t][j] = 0.f;

    const int a_lrow = lane & 15;
    const int a_koff = (lane >> 4) << 3;
    const int b_noff = (lane & 7) + ((lane >> 4) << 3);
    const int b_koff = ((lane >> 3) & 1) << 3;

    // per-chunk compute: 4 k-steps of 16 over a 64-k chunk
    auto compute_chunk = [&](uint32_t a_str2, int gk0, uint32_t bo) {
        #pragma unroll
        for (int ks = 0; ks < 4; ++ks) {
            int gk = gk0 + ks * 16;
            uint32_t af[2][4];
            #pragma unroll
            for (int mt = 0; mt < 2; ++mt) {
                uint32_t addr = sb
                    + (uint32_t)(wm * 32 + mt * 16 + a_lrow) * a_str2
                    + (uint32_t)(gk + a_koff) * 2;
                ldsm_x4(af[mt][0], af[mt][1], af[mt][2], af[mt][3], addr);
            }
            #pragma unroll
            for (int np = 0; np < 4; ++np) {
                uint32_t roff = (uint32_t)(wn * 64 + np * 16 + b_noff) * (SB_STR * 2)
                              + (uint32_t)(ks * 16 + b_koff) * 2;
                uint32_t r0, r1, r2, r3;
                ldsm_x4(r0, r1, r2, r3, sb + bo + roff);
                #pragma unroll
                for (int mt = 0; mt < 2; ++mt) {
                    mma_f16(acc[mt * 8 + np * 2],     af[mt], r0, r1);
                    mma_f16(acc[mt * 8 + np * 2 + 1], af[mt], r2, r3);
                }
            }
        }
    };

    // ---------------- unified loop: 6 chunks (2x W1 + 4x Wg) ----------------
    for (int g = 0; g < 6; ++g) {
        if (g + 2 < 6) stage_g(sb, tid, g + 2);
        if (g <= 3)      { CP_WAIT(2); }
        else if (g == 4) { CP_WAIT(1); }
        else             { CP_WAIT(0); }
        __syncthreads();
        if (g < 2) compute_chunk(SA_STR * 2, g * 64, b_offs[g % 3]);
        else       compute_chunk(SX_STR * 2, (g - 2) * 64, b_offs[g % 3]);
        __syncthreads();

        if (g == 1) {
            // epilogue 1: relu(acc + b1) -> fp16 sX (overwrites dead A), reset acc
            #pragma unroll
            for (int mt = 0; mt < 2; ++mt) {
                int rlo = wm * 32 + mt * 16 + (lane >> 2);
                #pragma unroll
                for (int nt = 0; nt < 8; ++nt) {
                    int col = wn * 64 + nt * 8 + (lane & 3) * 2;
                    float* a = acc[mt * 8 + nt];
                    float v0 = fmaxf(a[0] + b1s[col],     0.f);
                    float v1 = fmaxf(a[1] + b1s[col + 1], 0.f);
                    float v2 = fmaxf(a[2] + b1s[col],     0.f);
                    float v3 = fmaxf(a[3] + b1s[col + 1], 0.f);
                    *(uint32_t*)(smem + OFF_X + rlo * (SX_STR * 2) + col * 2)       = pack_h2(v0, v1);
                    *(uint32_t*)(smem + OFF_X + (rlo + 8) * (SX_STR * 2) + col * 2) = pack_h2(v2, v3);
                    a[0] = a[1] = a[2] = a[3] = 0.f;
                }
            }
            // visibility of X to all warps is covered by the sync at the top
            // of iteration g=2 (before its compute).
            __syncthreads();
        }
    }
    __syncthreads();

    // ---- epilogue 2: relu(acc + bg) -> bf16 into sX (overwrite) + stats ----
    float s_sum = 0.f, s_sq = 0.f;
    #pragma unroll
    for (int mt = 0; mt < 2; ++mt) {
        int rlo = wm * 32 + mt * 16 + (lane >> 2);
        #pragma unroll
        for (int nt = 0; nt < 8; ++nt) {
            int col = wn * 64 + nt * 8 + (lane & 3) * 2;
            float* a = acc[mt * 8 + nt];
            float v0 = fmaxf(a[0] + bgs[col],     0.f);
            float v1 = fmaxf(a[1] + bgs[col + 1], 0.f);
            float v2 = fmaxf(a[2] + bgs[col],     0.f);
            float v3 = fmaxf(a[3] + bgs[col + 1], 0.f);
            *(uint32_t*)(smem + OFF_X + rlo * (SX_STR * 2) + col * 2)       = pack_bf2(v0, v1);
            *(uint32_t*)(smem + OFF_X + (rlo + 8) * (SX_STR * 2) + col * 2) = pack_bf2(v2, v3);
            s_sum += (v0 + v1) + (v2 + v3);
            s_sq = fmaf(v0, v0, s_sq); s_sq = fmaf(v1, v1, s_sq);
            s_sq = fmaf(v2, v2, s_sq); s_sq = fmaf(v3, v3, s_sq);
        }
    }
    __syncthreads();

    // ---- coalesced copy sX -> g_Xg: 128 rows x 32 uint4 = 4096; 8 iters ----
    #pragma unroll
    for (int it = 0; it < 8; ++it) {
        int idx = tid + it * THREADS;
        int r = idx >> 5, q = idx & 31;
        uint4 v = *(uint4*)(smem + OFF_X + r * (SX_STR * 2) + q * 16);
        *(uint4*)((char*)g_Xg + (row0 + (size_t)r) * 512 + q * 16) = v;
    }

    // ---- block-reduce stats ----
    float* red = (float*)(smem + OFF_RED);
    red[tid] = s_sum; red[THREADS + tid] = s_sq;
    __syncthreads();
    for (int o = THREADS / 2; o > 0; o >>= 1) {
        if (tid < o) {
            red[tid] += red[tid + o];
            red[THREADS + tid] += red[THREADS + tid + o];
        }
        __syncthreads();
    }
    if (tid == 0) {
        atomicAdd(&g_sum_d,   (double)red[0]);
        atomicAdd(&g_sumsq_d, (double)red[THREADS]);
    }
}

// ---------------------------------------------------------------------------
// Gated pooling over bf16 Xg; finalize folded in. 512 blocks, 4-row ILP.
__global__ __launch_bounds__(256)
void pool_kernel(const float* __restrict__ ln_w, const float* __restrict__ ln_b,
                 const float* __restrict__ Wgate, const float* __restrict__ bgate)
{
    __shared__ float blk[HID];
    __shared__ float s_mu, s_inv;
    const int lane = threadIdx.x & 31;
    const int warp = (blockIdx.x * blockDim.x + threadIdx.x) >> 5;
    const int nwarps = (gridDim.x * blockDim.x) >> 5;   // 4096 warps
    for (int i = threadIdx.x; i < HID; i += blockDim.x) blk[i] = 0.f;
    if (threadIdx.x == 0) {
        double M = (double)N_NODES * (double)HID;
        double mu  = g_sum_d / M;
        double var = g_sumsq_d / M - mu * mu;
        if (var < 0.0) var = 0.0;
        s_mu  = (float)mu;
        s_inv = (float)(1.0 / (sqrt(var) + (double)LN_EPS));
    }
    __syncthreads();

    const float mu = s_mu, inv = s_inv;
    const int c0 = lane * 8;
    float lw[8], lb[8], wg[8], pp[8];
    #pragma unroll
    for (int j = 0; j < 8; ++j) {
        lw[j] = ln_w[c0 + j] * inv;
        lb[j] = ln_b[c0 + j];
        wg[j] = Wgate[c0 + j];
        pp[j] = 0.f;
    }
    const float bg0 = bgate[0];

    for (int r = warp * 4; r < N_NODES; r += nwarps * 4) {
        uint4 va[4];
        #pragma unroll
        for (int s = 0; s < 4; ++s)
            va[s] = *(const uint4*)((const char*)g_Xg + (size_t)(r + s) * 512 + c0 * 2);
        float x[4][8];
        #pragma unroll
        for (int s = 0; s < 4; ++s) {
            const uint32_t* pv = (const uint32_t*)&va[s];
            #pragma unroll
            for (int q = 0; q < 4; ++q) {
                float2 f = __bfloat1622float2(*(const __nv_bfloat162*)&pv[q]);
                x[s][2*q] = f.x; x[s][2*q+1] = f.y;
            }
        }
        float d[4] = {0.f, 0.f, 0.f, 0.f};
        #pragma unroll
        for (int s = 0; s < 4; ++s)
            #pragma unroll
            for (int j = 0; j < 8; ++j) {
                x[s][j] = fmaf(x[s][j] - mu, lw[j], lb[j]);
                d[s] = fmaf(x[s][j], wg[j], d[s]);
            }
        #pragma unroll
        for (int o = 16; o > 0; o >>= 1) {
            #pragma unroll
            for (int s = 0; s < 4; ++s)
                d[s] += __shfl_xor_sync(0xffffffffu, d[s], o);
        }
        float g[4];
        #pragma unroll
        for (int s = 0; s < 4; ++s)
            g[s] = 1.f / (1.f + __expf(-(d[s] + bg0)));
        #pragma unroll
        for (int s = 0; s < 4; ++s)
            #pragma unroll
            for (int j = 0; j < 8; ++j)
                pp[j] = fmaf(g[s], x[s][j], pp[j]);
    }
    #pragma unroll
    for (int j = 0; j < 8; ++j) atomicAdd(&blk[c0 + j], pp[j]);
    __syncthreads();
    for (int i = threadIdx.x; i < HID; i += blockDim.x)
        atomicAdd(&g_pooled[i], (double)blk[i]);
}

// ---------------------------------------------------------------------------
// GEMV layers, parallel across SMs. Block = 256 threads: 32 outputs x 8 k-slices.
template <int K, int N, bool IN_D>
__global__ __launch_bounds__(256)
void gemv_relu_kernel(const void* __restrict__ in_v, const float* __restrict__ W,
                      const float* __restrict__ b, float* __restrict__ out)
{
    __shared__ float sin[K];
    __shared__ float sred[256];
    const int tid = threadIdx.x;
    const int tx = tid & 31, ty = tid >> 5;
    const int n = blockIdx.x * 32 + tx;
    for (int i = tid; i < K; i += 256)
        sin[i] = IN_D ? (float)((const double*)in_v)[i] : ((const float*)in_v)[i];
    __syncthreads();
    float s = 0.f;
    #pragma unroll 4
    for (int k = ty; k < K; k += 8)
        s = fmaf(sin[k], W[(size_t)k * N + n], s);
    sred[tid] = s;
    __syncthreads();
    #pragma unroll
    for (int o = 4; o > 0; o >>= 1) {
        if (ty < o) sred[tid] += sred[tid + o * 32];
        __syncthreads();
    }
    if (ty == 0) out[n] = fmaxf(sred[tx] + b[n], 0.f);
}

// ---------------------------------------------------------------------------
// value = h3 . Wv + bv (redundant per block, L2-resident) then out = value*mask.
__global__ __launch_bounds__(256)
void bcast_kernel(const float* __restrict__ Wv, const float* __restrict__ bv,
                  const float* __restrict__ mask, float* __restrict__ out)
{
    __shared__ float red[256];
    const int t = threadIdx.x;
    red[t] = g_h3[t] * Wv[t] + g_h3[t + 256] * Wv[t + 256];
    __syncthreads();
    #pragma unroll
    for (int o = 128; o > 0; o >>= 1) {
        if (t < o) red[t] += red[t + o];
        __syncthreads();
    }
    float value = red[0] + bv[0];
    int i = blockIdx.x * 256 + t;
    if (i < N_NODES) out[i] = value * mask[i];
}

// ---------------------------------------------------------------------------
extern "C" void kernel_launch(void* const* d_in, const int* in_sizes, int n_in,
                              void* d_out, int out_size)
{
    const float* obs   = (const float*)d_in[0];
    const float* mask  = (const float*)d_in[1];
    // d_in[2] = edge_index (self-loops only -> GCN == dense GEMM, see header)
    const float* W1    = (const float*)d_in[3];
    const float* b1    = (const float*)d_in[4];
    const float* Wg    = (const float*)d_in[5];
    const float* bg    = (const float*)d_in[6];
    const float* ln_w  = (const float*)d_in[7];
    const float* ln_b  = (const float*)d_in[8];
    const float* Wgate = (const float*)d_in[9];
    const float* bgate = (const float*)d_in[10];
    const float* Wd    = (const float*)d_in[11];
    const float* bd    = (const float*)d_in[12];
    const float* Wp1   = (const float*)d_in[13];
    const float* bp1   = (const float*)d_in[14];
    const float* Wp2   = (const float*)d_in[15];
    const float* bp2   = (const float*)d_in[16];
    const float* Wv    = (const float*)d_in[17];
    const float* bv    = (const float*)d_in[18];
    float* out = (float*)d_out;

    cudaFuncSetAttribute(fused_gemm_kernel,
                         cudaFuncAttributeMaxDynamicSharedMemorySize, SMEM_TOTAL);

    float* d_h1; cudaGetSymbolAddress((void**)&d_h1, g_h1);
    float* d_h2; cudaGetSymbolAddress((void**)&d_h2, g_h2);
    float* d_h3; cudaGetSymbolAddress((void**)&d_h3, g_h3);
    double* d_pooled; cudaGetSymbolAddress((void**)&d_pooled, g_pooled);

    prep_zero_kernel<<<1, 256>>>();
    prep_w_kernel<<<(HID * F_DIM + HID * HID + 255) / 256, 256>>>(W1, Wg);
    fused_gemm_kernel<<<N_NODES / BM, THREADS, SMEM_TOTAL>>>(obs, b1, bg);
    pool_kernel<<<512, 256>>>(ln_w, ln_b, Wgate, bgate);                     // 4th launch
    gemv_relu_kernel<HID, HID, true ><<<HID / 32, 256>>>(d_pooled, Wd,  bd,  d_h1);
    gemv_relu_kernel<HID, POL, false><<<POL / 32, 256>>>(d_h1,     Wp1, bp1, d_h2);
    gemv_relu_kernel<POL, POL, false><<<POL / 32, 256>>>(d_h2,     Wp2, bp2, d_h3);
    bcast_kernel<<<(N_NODES + 255) / 256, 256>>>(Wv, bv, mask, out);
}

// round 14
// speedup vs baseline: 1.0208x; 1.0208x over previous
#include <cuda_runtime.h>
#include <cuda_bf16.h>
#include <cuda_fp16.h>
#include <math.h>
#include <stdint.h>

// Graph_Critic_Model on GB300 (plain sm_103 target: no tcgen05; HMMA mma.sync path).
// Self-loop-only graph => GCNConv collapses to dense GEMM:
//   X  = relu(obs @ W1 + b1)   [131072,256]
//   Xg = relu(X @ Wg + bg)     [131072,256]
//   global LN over all elements; sigmoid-gated pooling; tiny MLP; broadcast.
// Precision (R12-proven): fp16 weights+activations, fp32 accumulate; Xg bf16.
// R14: fused GEMM = exact R12 config (98.4us best). Pool grid 512 -> 1024
//      blocks (pool is latency-bound at 2.07TB/s, 26% HBM: double the MLP).

#define N_NODES 131072
#define F_DIM   128
#define HID     256
#define POL     512
#define LN_EPS  1e-5f

#define BM      128         // rows per CTA
#define THREADS 512         // 16 warps: wm = wid&3 (32 rows), wn = wid>>2 (64 cols)

// smem strides (fp16 elems); pitches 272/144/528 bytes -> conflict-free ldmatrix
#define SA_STR 136
#define SB_STR 72           // 64-k weight chunk rows (144B pitch)
#define SX_STR 264

// smem byte offsets
#define OFF_A    0                    // 34816
#define OFF_B0   34816                // 36864 each buffer
#define OFF_B1   71680
#define OFF_X    108544               // 67584
#define OFF_BB1  176128               // 1024 (b1 floats)
#define OFF_BBG  177152               // 1024 (bg floats)
#define OFF_RED  178176               // 4096
#define SMEM_TOTAL 182272

// ---------------- helpers ----------------
__device__ __forceinline__ uint32_t smem_u32(const void* p) {
    uint32_t a;
    asm("{ .reg .u64 t; cvta.to.shared.u64 t, %1; cvt.u32.u64 %0, t; }" : "=r"(a) : "l"(p));
    return a;
}
__device__ __forceinline__ uint32_t pack_h2(float lo, float hi) {
    __half2 h = __floats2half2_rn(lo, hi);
    return *reinterpret_cast<uint32_t*>(&h);
}
__device__ __forceinline__ uint32_t pack_bf2(float lo, float hi) {
    __nv_bfloat162 h = __floats2bfloat162_rn(lo, hi);
    return *reinterpret_cast<uint32_t*>(&h);
}
__device__ __forceinline__ void ldsm_x4(uint32_t& r0, uint32_t& r1, uint32_t& r2, uint32_t& r3,
                                        uint32_t addr) {
    asm volatile("ldmatrix.sync.aligned.m8n8.x4.shared.b16 {%0,%1,%2,%3}, [%4];"
                 : "=r"(r0), "=r"(r1), "=r"(r2), "=r"(r3) : "r"(addr));
}
__device__ __forceinline__ void mma_f16(float* d, const uint32_t* a, uint32_t b0, uint32_t b1) {
    asm volatile("mma.sync.aligned.m16n8k16.row.col.f32.f16.f16.f32 "
                 "{%0,%1,%2,%3}, {%4,%5,%6,%7}, {%8,%9}, {%0,%1,%2,%3};"
                 : "+f"(d[0]), "+f"(d[1]), "+f"(d[2]), "+f"(d[3])
                 : "r"(a[0]), "r"(a[1]), "r"(a[2]), "r"(a[3]), "r"(b0), "r"(b1));
}
__device__ __forceinline__ void cp16(uint32_t dst, const void* src) {
    asm volatile("cp.async.cg.shared.global [%0], [%1], 16;" :: "r"(dst), "l"(src));
}
#define CP_COMMIT() asm volatile("cp.async.commit_group;" ::: "memory")
#define CP_WAIT(n)  asm volatile("cp.async.wait_group %0;" :: "n"(n) : "memory")

// ---------------- device scratch ----------------
__device__ __align__(16) __nv_bfloat16 g_Xg[(size_t)N_NODES * HID];   // 64MB
__device__ __align__(16) __half g_W1T[HID * F_DIM];                   // [n][k] fp16
__device__ __align__(16) __half g_WgT[HID * HID];                     // [n][k] fp16
__device__ double g_sum_d, g_sumsq_d;
__device__ double g_pooled[HID];
__device__ float  g_h1[HID];
__device__ float  g_h2[POL];
__device__ float  g_h3[POL];

// ---------------------------------------------------------------------------
__global__ void prep_zero_kernel() {
    int t = threadIdx.x;
    if (t == 0) { g_sum_d = 0.0; g_sumsq_d = 0.0; }
    if (t < HID) g_pooled[t] = 0.0;
}
__global__ void prep_w1_kernel(const float* __restrict__ W1) {
    int i = blockIdx.x * blockDim.x + threadIdx.x;
    if (i < HID * F_DIM) {                        // W1 is [128 k][256 n]
        int n = i >> 7, k = i & 127;
        g_W1T[i] = __float2half_rn(W1[k * HID + n]);
    }
}
__global__ void prep_wg_kernel(const float* __restrict__ Wg) {
    int j = blockIdx.x * blockDim.x + threadIdx.x;
    if (j < HID * HID) {                          // Wg is [256 k][256 n]
        int n = j >> 8, k = j & 255;
        g_WgT[j] = __float2half_rn(Wg[k * HID + n]);
    }
}

// ---------------------------------------------------------------------------
// stage one 64-k chunk of an fp16 weight array via cp.async.
// Buffer: [256 n][64 k] fp16, row pitch 144B.
__device__ __forceinline__ void stage_chunk(uint32_t sb, int tid, uint32_t off,
                                            const __half* __restrict__ src,
                                            int kpitch, int c) {
    #pragma unroll
    for (int i = tid; i < 2048; i += THREADS) {
        int n = i >> 3, q = i & 7;                // 8 x 16B per 64-k row
        uint32_t d = (uint32_t)(n * (SB_STR * 2) + q * 16);
        const char* s = (const char*)(src + (size_t)n * kpitch + c * 64) + q * 16;
        cp16(sb + off + d, s);
    }
    CP_COMMIT();
}

// ---------------------------------------------------------------------------
// Fused GEMM1+GEMM2 per 128-row tile; HMMA fp16, fp32 accumulate.
// 16 warps x (32x64) tiles; 64-k chunks double-buffered (6 iterations total).
__global__ __launch_bounds__(THREADS, 1)
void fused_gemm_kernel(const float* __restrict__ obs,
                       const float* __restrict__ b1, const float* __restrict__ bg)
{
    extern __shared__ char smem[];
    const uint32_t sb = smem_u32(smem);
    const int tid  = threadIdx.x;
    const int lane = tid & 31;
    const int wid  = tid >> 5;
    const int wm   = wid & 3;        // row group: 32 rows
    const int wn   = wid >> 2;       // col group: 64 cols
    const size_t row0 = (size_t)blockIdx.x * BM;

    const uint32_t b_off[2] = {OFF_B0, OFF_B1};

    // prefetch W1 chunk 0 -> buffer 0 (overlaps A staging below)
    stage_chunk(sb, tid, OFF_B0, g_W1T, F_DIM, 0);

    float* b1s = (float*)(smem + OFF_BB1);
    float* bgs = (float*)(smem + OFF_BBG);
    if (tid < 256) { b1s[tid] = b1[tid]; bgs[tid] = bg[tid]; }

    // ---- stage obs [128 x 128] fp32 -> fp16 into sA ----
    const float4* obs4 = reinterpret_cast<const float4*>(obs + row0 * F_DIM);
    #pragma unroll
    for (int i = tid; i < 128 * 32; i += THREADS) {
        int r = i >> 5, c4 = i & 31;
        float4 v = obs4[i];
        uint2 p = make_uint2(pack_h2(v.x, v.y), pack_h2(v.z, v.w));
        *(uint2*)(smem + OFF_A + r * (SA_STR * 2) + c4 * 8) = p;
    }

    float acc[16][4];
    #pragma unroll
    for (int t = 0; t < 16; ++t)
        #pragma unroll
        for (int j = 0; j < 4; ++j) acc[t][j] = 0.f;

    const int a_lrow = lane & 15;
    const int a_koff = (lane >> 4) << 3;
    const int b_noff = (lane & 7) + ((lane >> 4) << 3);
    const int b_koff = ((lane >> 3) & 1) << 3;

    // per-chunk compute: 4 k-steps of 16 over a 64-k chunk
    auto compute_chunk = [&](uint32_t a_off, uint32_t a_str2, int gk0, uint32_t bo) {
        #pragma unroll
        for (int ks = 0; ks < 4; ++ks) {
            int gk = gk0 + ks * 16;
            uint32_t af[2][4];
            #pragma unroll
            for (int mt = 0; mt < 2; ++mt) {
                uint32_t addr = sb + a_off
                    + (uint32_t)(wm * 32 + mt * 16 + a_lrow) * a_str2
                    + (uint32_t)(gk + a_koff) * 2;
                ldsm_x4(af[mt][0], af[mt][1], af[mt][2], af[mt][3], addr);
            }
            #pragma unroll
            for (int np = 0; np < 4; ++np) {
                uint32_t roff = (uint32_t)(wn * 64 + np * 16 + b_noff) * (SB_STR * 2)
                              + (uint32_t)(ks * 16 + b_koff) * 2;
                uint32_t r0, r1, r2, r3;
                ldsm_x4(r0, r1, r2, r3, sb + bo + roff);
                #pragma unroll
                for (int mt = 0; mt < 2; ++mt) {
                    mma_f16(acc[mt * 8 + np * 2],     af[mt], r0, r1);
                    mma_f16(acc[mt * 8 + np * 2 + 1], af[mt], r2, r3);
                }
            }
        }
    };

    // ---------------- GEMM1: K=128, 2 chunks of 64 ----------------
    for (int c = 0; c < 2; ++c) {
        int nb = (c + 1) & 1;
        if (c < 1) stage_chunk(sb, tid, b_off[nb], g_W1T, F_DIM, 1);
        else       stage_chunk(sb, tid, b_off[nb], g_WgT, HID, 0);
        CP_WAIT(1);
        __syncthreads();
        compute_chunk(OFF_A, SA_STR * 2, c * 64, b_off[c & 1]);
        __syncthreads();
    }

    // ---- epilogue 1: relu(acc + b1) -> fp16 sX, reset acc ----
    #pragma unroll
    for (int mt = 0; mt < 2; ++mt) {
        int rlo = wm * 32 + mt * 16 + (lane >> 2);
        #pragma unroll
        for (int nt = 0; nt < 8; ++nt) {
            int col = wn * 64 + nt * 8 + (lane & 3) * 2;
            float* a = acc[mt * 8 + nt];
            float v0 = fmaxf(a[0] + b1s[col],     0.f);
            float v1 = fmaxf(a[1] + b1s[col + 1], 0.f);
            float v2 = fmaxf(a[2] + b1s[col],     0.f);
            float v3 = fmaxf(a[3] + b1s[col + 1], 0.f);
            *(uint32_t*)(smem + OFF_X + rlo * (SX_STR * 2) + col * 2)       = pack_h2(v0, v1);
            *(uint32_t*)(smem + OFF_X + (rlo + 8) * (SX_STR * 2) + col * 2) = pack_h2(v2, v3);
            a[0] = a[1] = a[2] = a[3] = 0.f;
        }
    }

    // ---------------- GEMM2: K=256, 4 chunks (g = 2..5) ----------------
    for (int c = 0; c < 4; ++c) {
        int g = 2 + c;
        if (c < 3) {
            int nb = (g + 1) & 1;
            stage_chunk(sb, tid, b_off[nb], g_WgT, HID, c + 1);
            CP_WAIT(1);
        } else {
            CP_WAIT(0);
        }
        __syncthreads();
        compute_chunk(OFF_X, SX_STR * 2, c * 64, b_off[g & 1]);
        __syncthreads();
    }
    __syncthreads();   // everyone done reading sX before overwrite below

    // ---- epilogue 2: relu(acc + bg) -> bf16 into sX (overwrite) + stats ----
    float s_sum = 0.f, s_sq = 0.f;
    #pragma unroll
    for (int mt = 0; mt < 2; ++mt) {
        int rlo = wm * 32 + mt * 16 + (lane >> 2);
        #pragma unroll
        for (int nt = 0; nt < 8; ++nt) {
            int col = wn * 64 + nt * 8 + (lane & 3) * 2;
            float* a = acc[mt * 8 + nt];
            float v0 = fmaxf(a[0] + bgs[col],     0.f);
            float v1 = fmaxf(a[1] + bgs[col + 1], 0.f);
            float v2 = fmaxf(a[2] + bgs[col],     0.f);
            float v3 = fmaxf(a[3] + bgs[col + 1], 0.f);
            *(uint32_t*)(smem + OFF_X + rlo * (SX_STR * 2) + col * 2)       = pack_bf2(v0, v1);
            *(uint32_t*)(smem + OFF_X + (rlo + 8) * (SX_STR * 2) + col * 2) = pack_bf2(v2, v3);
            s_sum += (v0 + v1) + (v2 + v3);
            s_sq = fmaf(v0, v0, s_sq); s_sq = fmaf(v1, v1, s_sq);
            s_sq = fmaf(v2, v2, s_sq); s_sq = fmaf(v3, v3, s_sq);
        }
    }
    __syncthreads();

    // ---- coalesced copy sX -> g_Xg: 128 rows x 32 uint4 = 4096; 8 iters ----
    #pragma unroll
    for (int it = 0; it < 8; ++it) {
        int idx = tid + it * THREADS;
        int r = idx >> 5, q = idx & 31;
        uint4 v = *(uint4*)(smem + OFF_X + r * (SX_STR * 2) + q * 16);
        *(uint4*)((char*)g_Xg + (row0 + (size_t)r) * 512 + q * 16) = v;
    }

    // ---- block-reduce stats ----
    float* red = (float*)(smem + OFF_RED);
    red[tid] = s_sum; red[THREADS + tid] = s_sq;
    __syncthreads();
    for (int o = THREADS / 2; o > 0; o >>= 1) {
        if (tid < o) {
            red[tid] += red[tid + o];
            red[THREADS + tid] += red[THREADS + tid + o];
        }
        __syncthreads();
    }
    if (tid == 0) {
        atomicAdd(&g_sum_d,   (double)red[0]);
        atomicAdd(&g_sumsq_d, (double)red[THREADS]);
    }
}

// ---------------------------------------------------------------------------
// Gated pooling over bf16 Xg; finalize folded in. 1024 blocks, 4-row ILP
// (pool is latency-bound: double the warp count -> double the MLP).
__global__ __launch_bounds__(256)
void pool_kernel(const float* __restrict__ ln_w, const float* __restrict__ ln_b,
                 const float* __restrict__ Wgate, const float* __restrict__ bgate)
{
    __shared__ float blk[HID];
    __shared__ float s_mu, s_inv;
    const int lane = threadIdx.x & 31;
    const int warp = (blockIdx.x * blockDim.x + threadIdx.x) >> 5;
    const int nwarps = (gridDim.x * blockDim.x) >> 5;   // 8192 warps
    for (int i = threadIdx.x; i < HID; i += blockDim.x) blk[i] = 0.f;
    if (threadIdx.x == 0) {
        double M = (double)N_NODES * (double)HID;
        double mu  = g_sum_d / M;
        double var = g_sumsq_d / M - mu * mu;
        if (var < 0.0) var = 0.0;
        s_mu  = (float)mu;
        s_inv = (float)(1.0 / (sqrt(var) + (double)LN_EPS));
    }
    __syncthreads();

    const float mu = s_mu, inv = s_inv;
    const int c0 = lane * 8;
    float lw[8], lb[8], wg[8], pp[8];
    #pragma unroll
    for (int j = 0; j < 8; ++j) {
        lw[j] = ln_w[c0 + j] * inv;
        lb[j] = ln_b[c0 + j];
        wg[j] = Wgate[c0 + j];
        pp[j] = 0.f;
    }
    const float bg0 = bgate[0];

    // 131072 rows / (8192 warps * 4 rows) = 4 iterations
    for (int r = warp * 4; r < N_NODES; r += nwarps * 4) {
        uint4 va[4];
        #pragma unroll
        for (int s = 0; s < 4; ++s)
            va[s] = *(const uint4*)((const char*)g_Xg + (size_t)(r + s) * 512 + c0 * 2);
        float x[4][8];
        #pragma unroll
        for (int s = 0; s < 4; ++s) {
            const uint32_t* pv = (const uint32_t*)&va[s];
            #pragma unroll
            for (int q = 0; q < 4; ++q) {
                float2 f = __bfloat1622float2(*(const __nv_bfloat162*)&pv[q]);
                x[s][2*q] = f.x; x[s][2*q+1] = f.y;
            }
        }
        float d[4] = {0.f, 0.f, 0.f, 0.f};
        #pragma unroll
        for (int s = 0; s < 4; ++s)
            #pragma unroll
            for (int j = 0; j < 8; ++j) {
                x[s][j] = fmaf(x[s][j] - mu, lw[j], lb[j]);
                d[s] = fmaf(x[s][j], wg[j], d[s]);
            }
        #pragma unroll
        for (int o = 16; o > 0; o >>= 1) {
            #pragma unroll
            for (int s = 0; s < 4; ++s)
                d[s] += __shfl_xor_sync(0xffffffffu, d[s], o);
        }
        float g[4];
        #pragma unroll
        for (int s = 0; s < 4; ++s)
            g[s] = 1.f / (1.f + __expf(-(d[s] + bg0)));
        #pragma unroll
        for (int s = 0; s < 4; ++s)
            #pragma unroll
            for (int j = 0; j < 8; ++j)
                pp[j] = fmaf(g[s], x[s][j], pp[j]);
    }
    #pragma unroll
    for (int j = 0; j < 8; ++j) atomicAdd(&blk[c0 + j], pp[j]);
    __syncthreads();
    for (int i = threadIdx.x; i < HID; i += blockDim.x)
        atomicAdd(&g_pooled[i], (double)blk[i]);
}

// ---------------------------------------------------------------------------
// GEMV layers, parallel across SMs. Block = 256 threads: 32 outputs x 8 k-slices.
template <int K, int N, bool IN_D>
__global__ __launch_bounds__(256)
void gemv_relu_kernel(const void* __restrict__ in_v, const float* __restrict__ W,
                      const float* __restrict__ b, float* __restrict__ out)
{
    __shared__ float sin[K];
    __shared__ float sred[256];
    const int tid = threadIdx.x;
    const int tx = tid & 31, ty = tid >> 5;
    const int n = blockIdx.x * 32 + tx;
    for (int i = tid; i < K; i += 256)
        sin[i] = IN_D ? (float)((const double*)in_v)[i] : ((const float*)in_v)[i];
    __syncthreads();
    float s = 0.f;
    #pragma unroll 4
    for (int k = ty; k < K; k += 8)
        s = fmaf(sin[k], W[(size_t)k * N + n], s);
    sred[tid] = s;
    __syncthreads();
    #pragma unroll
    for (int o = 4; o > 0; o >>= 1) {
        if (ty < o) sred[tid] += sred[tid + o * 32];
        __syncthreads();
    }
    if (ty == 0) out[n] = fmaxf(sred[tx] + b[n], 0.f);
}

// ---------------------------------------------------------------------------
// value = h3 . Wv + bv (redundant per block, L2-resident) then out = value*mask.
__global__ __launch_bounds__(256)
void bcast_kernel(const float* __restrict__ Wv, const float* __restrict__ bv,
                  const float* __restrict__ mask, float* __restrict__ out)
{
    __shared__ float red[256];
    const int t = threadIdx.x;
    red[t] = g_h3[t] * Wv[t] + g_h3[t + 256] * Wv[t + 256];
    __syncthreads();
    #pragma unroll
    for (int o = 128; o > 0; o >>= 1) {
        if (t < o) red[t] += red[t + o];
        __syncthreads();
    }
    float value = red[0] + bv[0];
    int i = blockIdx.x * 256 + t;
    if (i < N_NODES) out[i] = value * mask[i];
}

// ---------------------------------------------------------------------------
extern "C" void kernel_launch(void* const* d_in, const int* in_sizes, int n_in,
                              void* d_out, int out_size)
{
    const float* obs   = (const float*)d_in[0];
    const float* mask  = (const float*)d_in[1];
    // d_in[2] = edge_index (self-loops only -> GCN == dense GEMM, see header)
    const float* W1    = (const float*)d_in[3];
    const float* b1    = (const float*)d_in[4];
    const float* Wg    = (const float*)d_in[5];
    const float* bg    = (const float*)d_in[6];
    const float* ln_w  = (const float*)d_in[7];
    const float* ln_b  = (const float*)d_in[8];
    const float* Wgate = (const float*)d_in[9];
    const float* bgate = (const float*)d_in[10];
    const float* Wd    = (const float*)d_in[11];
    const float* bd    = (const float*)d_in[12];
    const float* Wp1   = (const float*)d_in[13];
    const float* bp1   = (const float*)d_in[14];
    const float* Wp2   = (const float*)d_in[15];
    const float* bp2   = (const float*)d_in[16];
    const float* Wv    = (const float*)d_in[17];
    const float* bv    = (const float*)d_in[18];
    float* out = (float*)d_out;

    cudaFuncSetAttribute(fused_gemm_kernel,
                         cudaFuncAttributeMaxDynamicSharedMemorySize, SMEM_TOTAL);

    float* d_h1; cudaGetSymbolAddress((void**)&d_h1, g_h1);
    float* d_h2; cudaGetSymbolAddress((void**)&d_h2, g_h2);
    float* d_h3; cudaGetSymbolAddress((void**)&d_h3, g_h3);
    double* d_pooled; cudaGetSymbolAddress((void**)&d_pooled, g_pooled);

    prep_zero_kernel<<<1, 256>>>();
    prep_w1_kernel<<<(HID * F_DIM + 255) / 256, 256>>>(W1);
    prep_wg_kernel<<<(HID * HID + 255) / 256, 256>>>(Wg);
    fused_gemm_kernel<<<N_NODES / BM, THREADS, SMEM_TOTAL>>>(obs, b1, bg);
    pool_kernel<<<1024, 256>>>(ln_w, ln_b, Wgate, bgate);
    gemv_relu_kernel<HID, HID, true ><<<HID / 32, 256>>>(d_pooled, Wd,  bd,  d_h1);
    gemv_relu_kernel<HID, POL, false><<<POL / 32, 256>>>(d_h1,     Wp1, bp1, d_h2);
    gemv_relu_kernel<POL, POL, false><<<POL / 32, 256>>>(d_h2,     Wp2, bp2, d_h3);
    bcast_kernel<<<(N_NODES + 255) / 256, 256>>>(Wv, bv, mask, out);
}

// round 15
// speedup vs baseline: 1.0791x; 1.0570x over previous
#include <cuda_runtime.h>
#include <cuda_bf16.h>
#include <cuda_fp16.h>
#include <math.h>
#include <stdint.h>

// Graph_Critic_Model on GB300 (plain sm_103 target: no tcgen05; HMMA mma.sync path).
// Self-loop-only graph => GCNConv collapses to dense GEMM:
//   X  = relu(obs @ W1 + b1)   [131072,256]
//   Xg = relu(X @ Wg + bg)     [131072,256]
//   global LN over all elements; sigmoid-gated pooling; tiny MLP; broadcast.
// Precision (R12-proven): fp16 weights+activations, fp32 accumulate; Xg bf16.
// R15: exact R12 kernels (fused 98.4us, pool@512 32.4us); single merged prep
//      kernel (9 -> 7 launches; each small launch costs ~3-5us).

#define N_NODES 131072
#define F_DIM   128
#define HID     256
#define POL     512
#define LN_EPS  1e-5f

#define BM      128         // rows per CTA
#define THREADS 512         // 16 warps: wm = wid&3 (32 rows), wn = wid>>2 (64 cols)

// smem strides (fp16 elems); pitches 272/144/528 bytes -> conflict-free ldmatrix
#define SA_STR 136
#define SB_STR 72           // 64-k weight chunk rows (144B pitch)
#define SX_STR 264

// smem byte offsets
#define OFF_A    0                    // 34816
#define OFF_B0   34816                // 36864 each buffer
#define OFF_B1   71680
#define OFF_X    108544               // 67584
#define OFF_BB1  176128               // 1024 (b1 floats)
#define OFF_BBG  177152               // 1024 (bg floats)
#define OFF_RED  178176               // 4096
#define SMEM_TOTAL 182272

// ---------------- helpers ----------------
__device__ __forceinline__ uint32_t smem_u32(const void* p) {
    uint32_t a;
    asm("{ .reg .u64 t; cvta.to.shared.u64 t, %1; cvt.u32.u64 %0, t; }" : "=r"(a) : "l"(p));
    return a;
}
__device__ __forceinline__ uint32_t pack_h2(float lo, float hi) {
    __half2 h = __floats2half2_rn(lo, hi);
    return *reinterpret_cast<uint32_t*>(&h);
}
__device__ __forceinline__ uint32_t pack_bf2(float lo, float hi) {
    __nv_bfloat162 h = __floats2bfloat162_rn(lo, hi);
    return *reinterpret_cast<uint32_t*>(&h);
}
__device__ __forceinline__ void ldsm_x4(uint32_t& r0, uint32_t& r1, uint32_t& r2, uint32_t& r3,
                                        uint32_t addr) {
    asm volatile("ldmatrix.sync.aligned.m8n8.x4.shared.b16 {%0,%1,%2,%3}, [%4];"
                 : "=r"(r0), "=r"(r1), "=r"(r2), "=r"(r3) : "r"(addr));
}
__device__ __forceinline__ void mma_f16(float* d, const uint32_t* a, uint32_t b0, uint32_t b1) {
    asm volatile("mma.sync.aligned.m16n8k16.row.col.f32.f16.f16.f32 "
                 "{%0,%1,%2,%3}, {%4,%5,%6,%7}, {%8,%9}, {%0,%1,%2,%3};"
                 : "+f"(d[0]), "+f"(d[1]), "+f"(d[2]), "+f"(d[3])
                 : "r"(a[0]), "r"(a[1]), "r"(a[2]), "r"(a[3]), "r"(b0), "r"(b1));
}
__device__ __forceinline__ void cp16(uint32_t dst, const void* src) {
    asm volatile("cp.async.cg.shared.global [%0], [%1], 16;" :: "r"(dst), "l"(src));
}
#define CP_COMMIT() asm volatile("cp.async.commit_group;" ::: "memory")
#define CP_WAIT(n)  asm volatile("cp.async.wait_group %0;" :: "n"(n) : "memory")

// ---------------- device scratch ----------------
__device__ __align__(16) __nv_bfloat16 g_Xg[(size_t)N_NODES * HID];   // 64MB
__device__ __align__(16) __half g_W1T[HID * F_DIM];                   // [n][k] fp16
__device__ __align__(16) __half g_WgT[HID * HID];                     // [n][k] fp16
__device__ double g_sum_d, g_sumsq_d;
__device__ double g_pooled[HID];
__device__ float  g_h1[HID];
__device__ float  g_h2[POL];
__device__ float  g_h3[POL];

// ---------------------------------------------------------------------------
// single prep kernel: zero accumulators + convert both weights to fp16 [n][k]
__global__ void prep_kernel(const float* __restrict__ W1, const float* __restrict__ Wg) {
    int i = blockIdx.x * blockDim.x + threadIdx.x;
    if (i == 0) { g_sum_d = 0.0; g_sumsq_d = 0.0; }
    if (i < HID) g_pooled[i] = 0.0;
    if (i < HID * F_DIM) {                        // W1 is [128 k][256 n]
        int n = i >> 7, k = i & 127;
        g_W1T[i] = __float2half_rn(W1[k * HID + n]);
    }
    int j = i - HID * F_DIM;
    if (j >= 0 && j < HID * HID) {                // Wg is [256 k][256 n]
        int n = j >> 8, k = j & 255;
        g_WgT[j] = __float2half_rn(Wg[k * HID + n]);
    }
}

// ---------------------------------------------------------------------------
// stage one 64-k chunk of an fp16 weight array via cp.async.
// Buffer: [256 n][64 k] fp16, row pitch 144B.
__device__ __forceinline__ void stage_chunk(uint32_t sb, int tid, uint32_t off,
                                            const __half* __restrict__ src,
                                            int kpitch, int c) {
    #pragma unroll
    for (int i = tid; i < 2048; i += THREADS) {
        int n = i >> 3, q = i & 7;                // 8 x 16B per 64-k row
        uint32_t d = (uint32_t)(n * (SB_STR * 2) + q * 16);
        const char* s = (const char*)(src + (size_t)n * kpitch + c * 64) + q * 16;
        cp16(sb + off + d, s);
    }
    CP_COMMIT();
}

// ---------------------------------------------------------------------------
// Fused GEMM1+GEMM2 per 128-row tile; HMMA fp16, fp32 accumulate.
// 16 warps x (32x64) tiles; 64-k chunks double-buffered (6 iterations total).
__global__ __launch_bounds__(THREADS, 1)
void fused_gemm_kernel(const float* __restrict__ obs,
                       const float* __restrict__ b1, const float* __restrict__ bg)
{
    extern __shared__ char smem[];
    const uint32_t sb = smem_u32(smem);
    const int tid  = threadIdx.x;
    const int lane = tid & 31;
    const int wid  = tid >> 5;
    const int wm   = wid & 3;        // row group: 32 rows
    const int wn   = wid >> 2;       // col group: 64 cols
    const size_t row0 = (size_t)blockIdx.x * BM;

    const uint32_t b_off[2] = {OFF_B0, OFF_B1};

    // prefetch W1 chunk 0 -> buffer 0 (overlaps A staging below)
    stage_chunk(sb, tid, OFF_B0, g_W1T, F_DIM, 0);

    float* b1s = (float*)(smem + OFF_BB1);
    float* bgs = (float*)(smem + OFF_BBG);
    if (tid < 256) { b1s[tid] = b1[tid]; bgs[tid] = bg[tid]; }

    // ---- stage obs [128 x 128] fp32 -> fp16 into sA ----
    const float4* obs4 = reinterpret_cast<const float4*>(obs + row0 * F_DIM);
    #pragma unroll
    for (int i = tid; i < 128 * 32; i += THREADS) {
        int r = i >> 5, c4 = i & 31;
        float4 v = obs4[i];
        uint2 p = make_uint2(pack_h2(v.x, v.y), pack_h2(v.z, v.w));
        *(uint2*)(smem + OFF_A + r * (SA_STR * 2) + c4 * 8) = p;
    }

    float acc[16][4];
    #pragma unroll
    for (int t = 0; t < 16; ++t)
        #pragma unroll
        for (int j = 0; j < 4; ++j) acc[t][j] = 0.f;

    const int a_lrow = lane & 15;
    const int a_koff = (lane >> 4) << 3;
    const int b_noff = (lane & 7) + ((lane >> 4) << 3);
    const int b_koff = ((lane >> 3) & 1) << 3;

    // per-chunk compute: 4 k-steps of 16 over a 64-k chunk
    auto compute_chunk = [&](uint32_t a_off, uint32_t a_str2, int gk0, uint32_t bo) {
        #pragma unroll
        for (int ks = 0; ks < 4; ++ks) {
            int gk = gk0 + ks * 16;
            uint32_t af[2][4];
            #pragma unroll
            for (int mt = 0; mt < 2; ++mt) {
                uint32_t addr = sb + a_off
                    + (uint32_t)(wm * 32 + mt * 16 + a_lrow) * a_str2
                    + (uint32_t)(gk + a_koff) * 2;
                ldsm_x4(af[mt][0], af[mt][1], af[mt][2], af[mt][3], addr);
            }
            #pragma unroll
            for (int np = 0; np < 4; ++np) {
                uint32_t roff = (uint32_t)(wn * 64 + np * 16 + b_noff) * (SB_STR * 2)
                              + (uint32_t)(ks * 16 + b_koff) * 2;
                uint32_t r0, r1, r2, r3;
                ldsm_x4(r0, r1, r2, r3, sb + bo + roff);
                #pragma unroll
                for (int mt = 0; mt < 2; ++mt) {
                    mma_f16(acc[mt * 8 + np * 2],     af[mt], r0, r1);
                    mma_f16(acc[mt * 8 + np * 2 + 1], af[mt], r2, r3);
                }
            }
        }
    };

    // ---------------- GEMM1: K=128, 2 chunks of 64 ----------------
    for (int c = 0; c < 2; ++c) {
        int nb = (c + 1) & 1;
        if (c < 1) stage_chunk(sb, tid, b_off[nb], g_W1T, F_DIM, 1);
        else       stage_chunk(sb, tid, b_off[nb], g_WgT, HID, 0);
        CP_WAIT(1);
        __syncthreads();
        compute_chunk(OFF_A, SA_STR * 2, c * 64, b_off[c & 1]);
        __syncthreads();
    }

    // ---- epilogue 1: relu(acc + b1) -> fp16 sX, reset acc ----
    #pragma unroll
    for (int mt = 0; mt < 2; ++mt) {
        int rlo = wm * 32 + mt * 16 + (lane >> 2);
        #pragma unroll
        for (int nt = 0; nt < 8; ++nt) {
            int col = wn * 64 + nt * 8 + (lane & 3) * 2;
            float* a = acc[mt * 8 + nt];
            float v0 = fmaxf(a[0] + b1s[col],     0.f);
            float v1 = fmaxf(a[1] + b1s[col + 1], 0.f);
            float v2 = fmaxf(a[2] + b1s[col],     0.f);
            float v3 = fmaxf(a[3] + b1s[col + 1], 0.f);
            *(uint32_t*)(smem + OFF_X + rlo * (SX_STR * 2) + col * 2)       = pack_h2(v0, v1);
            *(uint32_t*)(smem + OFF_X + (rlo + 8) * (SX_STR * 2) + col * 2) = pack_h2(v2, v3);
            a[0] = a[1] = a[2] = a[3] = 0.f;
        }
    }

    // ---------------- GEMM2: K=256, 4 chunks (g = 2..5) ----------------
    for (int c = 0; c < 4; ++c) {
        int g = 2 + c;
        if (c < 3) {
            int nb = (g + 1) & 1;
            stage_chunk(sb, tid, b_off[nb], g_WgT, HID, c + 1);
            CP_WAIT(1);
        } else {
            CP_WAIT(0);
        }
        __syncthreads();
        compute_chunk(OFF_X, SX_STR * 2, c * 64, b_off[g & 1]);
        __syncthreads();
    }
    __syncthreads();   // everyone done reading sX before overwrite below

    // ---- epilogue 2: relu(acc + bg) -> bf16 into sX (overwrite) + stats ----
    float s_sum = 0.f, s_sq = 0.f;
    #pragma unroll
    for (int mt = 0; mt < 2; ++mt) {
        int rlo = wm * 32 + mt * 16 + (lane >> 2);
        #pragma unroll
        for (int nt = 0; nt < 8; ++nt) {
            int col = wn * 64 + nt * 8 + (lane & 3) * 2;
            float* a = acc[mt * 8 + nt];
            float v0 = fmaxf(a[0] + bgs[col],     0.f);
            float v1 = fmaxf(a[1] + bgs[col + 1], 0.f);
            float v2 = fmaxf(a[2] + bgs[col],     0.f);
            float v3 = fmaxf(a[3] + bgs[col + 1], 0.f);
            *(uint32_t*)(smem + OFF_X + rlo * (SX_STR * 2) + col * 2)       = pack_bf2(v0, v1);
            *(uint32_t*)(smem + OFF_X + (rlo + 8) * (SX_STR * 2) + col * 2) = pack_bf2(v2, v3);
            s_sum += (v0 + v1) + (v2 + v3);
            s_sq = fmaf(v0, v0, s_sq); s_sq = fmaf(v1, v1, s_sq);
            s_sq = fmaf(v2, v2, s_sq); s_sq = fmaf(v3, v3, s_sq);
        }
    }
    __syncthreads();

    // ---- coalesced copy sX -> g_Xg: 128 rows x 32 uint4 = 4096; 8 iters ----
    #pragma unroll
    for (int it = 0; it < 8; ++it) {
        int idx = tid + it * THREADS;
        int r = idx >> 5, q = idx & 31;
        uint4 v = *(uint4*)(smem + OFF_X + r * (SX_STR * 2) + q * 16);
        *(uint4*)((char*)g_Xg + (row0 + (size_t)r) * 512 + q * 16) = v;
    }

    // ---- block-reduce stats ----
    float* red = (float*)(smem + OFF_RED);
    red[tid] = s_sum; red[THREADS + tid] = s_sq;
    __syncthreads();
    for (int o = THREADS / 2; o > 0; o >>= 1) {
        if (tid < o) {
            red[tid] += red[tid + o];
            red[THREADS + tid] += red[THREADS + tid + o];
        }
        __syncthreads();
    }
    if (tid == 0) {
        atomicAdd(&g_sum_d,   (double)red[0]);
        atomicAdd(&g_sumsq_d, (double)red[THREADS]);
    }
}

// ---------------------------------------------------------------------------
// Gated pooling over bf16 Xg; finalize folded in. 512 blocks, 4-row ILP.
__global__ __launch_bounds__(256)
void pool_kernel(const float* __restrict__ ln_w, const float* __restrict__ ln_b,
                 const float* __restrict__ Wgate, const float* __restrict__ bgate)
{
    __shared__ float blk[HID];
    __shared__ float s_mu, s_inv;
    const int lane = threadIdx.x & 31;
    const int warp = (blockIdx.x * blockDim.x + threadIdx.x) >> 5;
    const int nwarps = (gridDim.x * blockDim.x) >> 5;   // 4096 warps
    for (int i = threadIdx.x; i < HID; i += blockDim.x) blk[i] = 0.f;
    if (threadIdx.x == 0) {
        double M = (double)N_NODES * (double)HID;
        double mu  = g_sum_d / M;
        double var = g_sumsq_d / M - mu * mu;
        if (var < 0.0) var = 0.0;
        s_mu  = (float)mu;
        s_inv = (float)(1.0 / (sqrt(var) + (double)LN_EPS));
    }
    __syncthreads();

    const float mu = s_mu, inv = s_inv;
    const int c0 = lane * 8;
    float lw[8], lb[8], wg[8], pp[8];
    #pragma unroll
    for (int j = 0; j < 8; ++j) {
        lw[j] = ln_w[c0 + j] * inv;
        lb[j] = ln_b[c0 + j];
        wg[j] = Wgate[c0 + j];
        pp[j] = 0.f;
    }
    const float bg0 = bgate[0];

    for (int r = warp * 4; r < N_NODES; r += nwarps * 4) {
        uint4 va[4];
        #pragma unroll
        for (int s = 0; s < 4; ++s)
            va[s] = *(const uint4*)((const char*)g_Xg + (size_t)(r + s) * 512 + c0 * 2);
        float x[4][8];
        #pragma unroll
        for (int s = 0; s < 4; ++s) {
            const uint32_t* pv = (const uint32_t*)&va[s];
            #pragma unroll
            for (int q = 0; q < 4; ++q) {
                float2 f = __bfloat1622float2(*(const __nv_bfloat162*)&pv[q]);
                x[s][2*q] = f.x; x[s][2*q+1] = f.y;
            }
        }
        float d[4] = {0.f, 0.f, 0.f, 0.f};
        #pragma unroll
        for (int s = 0; s < 4; ++s)
            #pragma unroll
            for (int j = 0; j < 8; ++j) {
                x[s][j] = fmaf(x[s][j] - mu, lw[j], lb[j]);
                d[s] = fmaf(x[s][j], wg[j], d[s]);
            }
        #pragma unroll
        for (int o = 16; o > 0; o >>= 1) {
            #pragma unroll
            for (int s = 0; s < 4; ++s)
                d[s] += __shfl_xor_sync(0xffffffffu, d[s], o);
        }
        float g[4];
        #pragma unroll
        for (int s = 0; s < 4; ++s)
            g[s] = 1.f / (1.f + __expf(-(d[s] + bg0)));
        #pragma unroll
        for (int s = 0; s < 4; ++s)
            #pragma unroll
            for (int j = 0; j < 8; ++j)
                pp[j] = fmaf(g[s], x[s][j], pp[j]);
    }
    #pragma unroll
    for (int j = 0; j < 8; ++j) atomicAdd(&blk[c0 + j], pp[j]);
    __syncthreads();
    for (int i = threadIdx.x; i < HID; i += blockDim.x)
        atomicAdd(&g_pooled[i], (double)blk[i]);
}

// ---------------------------------------------------------------------------
// GEMV layers, parallel across SMs. Block = 256 threads: 32 outputs x 8 k-slices.
template <int K, int N, bool IN_D>
__global__ __launch_bounds__(256)
void gemv_relu_kernel(const void* __restrict__ in_v, const float* __restrict__ W,
                      const float* __restrict__ b, float* __restrict__ out)
{
    __shared__ float sin[K];
    __shared__ float sred[256];
    const int tid = threadIdx.x;
    const int tx = tid & 31, ty = tid >> 5;
    const int n = blockIdx.x * 32 + tx;
    for (int i = tid; i < K; i += 256)
        sin[i] = IN_D ? (float)((const double*)in_v)[i] : ((const float*)in_v)[i];
    __syncthreads();
    float s = 0.f;
    #pragma unroll 4
    for (int k = ty; k < K; k += 8)
        s = fmaf(sin[k], W[(size_t)k * N + n], s);
    sred[tid] = s;
    __syncthreads();
    #pragma unroll
    for (int o = 4; o > 0; o >>= 1) {
        if (ty < o) sred[tid] += sred[tid + o * 32];
        __syncthreads();
    }
    if (ty == 0) out[n] = fmaxf(sred[tx] + b[n], 0.f);
}

// ---------------------------------------------------------------------------
// value = h3 . Wv + bv (redundant per block, L2-resident) then out = value*mask.
__global__ __launch_bounds__(256)
void bcast_kernel(const float* __restrict__ Wv, const float* __restrict__ bv,
                  const float* __restrict__ mask, float* __restrict__ out)
{
    __shared__ float red[256];
    const int t = threadIdx.x;
    red[t] = g_h3[t] * Wv[t] + g_h3[t + 256] * Wv[t + 256];
    __syncthreads();
    #pragma unroll
    for (int o = 128; o > 0; o >>= 1) {
        if (t < o) red[t] += red[t + o];
        __syncthreads();
    }
    float value = red[0] + bv[0];
    int i = blockIdx.x * 256 + t;
    if (i < N_NODES) out[i] = value * mask[i];
}

// ---------------------------------------------------------------------------
extern "C" void kernel_launch(void* const* d_in, const int* in_sizes, int n_in,
                              void* d_out, int out_size)
{
    const float* obs   = (const float*)d_in[0];
    const float* mask  = (const float*)d_in[1];
    // d_in[2] = edge_index (self-loops only -> GCN == dense GEMM, see header)
    const float* W1    = (const float*)d_in[3];
    const float* b1    = (const float*)d_in[4];
    const float* Wg    = (const float*)d_in[5];
    const float* bg    = (const float*)d_in[6];
    const float* ln_w  = (const float*)d_in[7];
    const float* ln_b  = (const float*)d_in[8];
    const float* Wgate = (const float*)d_in[9];
    const float* bgate = (const float*)d_in[10];
    const float* Wd    = (const float*)d_in[11];
    const float* bd    = (const float*)d_in[12];
    const float* Wp1   = (const float*)d_in[13];
    const float* bp1   = (const float*)d_in[14];
    const float* Wp2   = (const float*)d_in[15];
    const float* bp2   = (const float*)d_in[16];
    const float* Wv    = (const float*)d_in[17];
    const float* bv    = (const float*)d_in[18];
    float* out = (float*)d_out;

    cudaFuncSetAttribute(fused_gemm_kernel,
                         cudaFuncAttributeMaxDynamicSharedMemorySize, SMEM_TOTAL);

    float* d_h1; cudaGetSymbolAddress((void**)&d_h1, g_h1);
    float* d_h2; cudaGetSymbolAddress((void**)&d_h2, g_h2);
    float* d_h3; cudaGetSymbolAddress((void**)&d_h3, g_h3);
    double* d_pooled; cudaGetSymbolAddress((void**)&d_pooled, g_pooled);

    prep_kernel<<<(HID * F_DIM + HID * HID + 255) / 256, 256>>>(W1, Wg);
    fused_gemm_kernel<<<N_NODES / BM, THREADS, SMEM_TOTAL>>>(obs, b1, bg);
    pool_kernel<<<512, 256>>>(ln_w, ln_b, Wgate, bgate);
    gemv_relu_kernel<HID, HID, true ><<<HID / 32, 256>>>(d_pooled, Wd,  bd,  d_h1);
    gemv_relu_kernel<HID, POL, false><<<POL / 32, 256>>>(d_h1,     Wp1, bp1, d_h2);
    gemv_relu_kernel<POL, POL, false><<<POL / 32, 256>>>(d_h2,     Wp2, bp2, d_h3);
    bcast_kernel<<<(N_NODES + 255) / 256, 256>>>(Wv, bv, mask, out);
}

// round 16
// speedup vs baseline: 1.1802x; 1.0937x over previous
#include <cuda_runtime.h>
#include <cuda_bf16.h>
#include <cuda_fp16.h>
#include <math.h>
#include <stdint.h>

// Graph_Critic_Model on GB300 (plain sm_103 target: no tcgen05; HMMA mma.sync path).
// Self-loop-only graph => GCNConv collapses to dense GEMM:
//   X  = relu(obs @ W1 + b1)   [131072,256]
//   Xg = relu(X @ Wg + bg)     [131072,256]
//   global LN over all elements; sigmoid-gated pooling; tiny MLP; broadcast.
// Precision (R12-proven): fp16 weights+activations, fp32 accumulate; Xg bf16.
// R16: pool prefetches MLP weights into L2 (gemvs were cold-DRAM latency-bound,
//      29GB/s, issue 3.5%); gemv uses 4 rotating accumulators (breaks the
//      serial fmaf chain). Fused GEMM + pool byte-identical to R15.

#define N_NODES 131072
#define F_DIM   128
#define HID     256
#define POL     512
#define LN_EPS  1e-5f

#define BM      128         // rows per CTA
#define THREADS 512         // 16 warps: wm = wid&3 (32 rows), wn = wid>>2 (64 cols)

// smem strides (fp16 elems); pitches 272/144/528 bytes -> conflict-free ldmatrix
#define SA_STR 136
#define SB_STR 72           // 64-k weight chunk rows (144B pitch)
#define SX_STR 264

// smem byte offsets
#define OFF_A    0                    // 34816
#define OFF_B0   34816                // 36864 each buffer
#define OFF_B1   71680
#define OFF_X    108544               // 67584
#define OFF_BB1  176128               // 1024 (b1 floats)
#define OFF_BBG  177152               // 1024 (bg floats)
#define OFF_RED  178176               // 4096
#define SMEM_TOTAL 182272

// ---------------- helpers ----------------
__device__ __forceinline__ uint32_t smem_u32(const void* p) {
    uint32_t a;
    asm("{ .reg .u64 t; cvta.to.shared.u64 t, %1; cvt.u32.u64 %0, t; }" : "=r"(a) : "l"(p));
    return a;
}
__device__ __forceinline__ uint32_t pack_h2(float lo, float hi) {
    __half2 h = __floats2half2_rn(lo, hi);
    return *reinterpret_cast<uint32_t*>(&h);
}
__device__ __forceinline__ uint32_t pack_bf2(float lo, float hi) {
    __nv_bfloat162 h = __floats2bfloat162_rn(lo, hi);
    return *reinterpret_cast<uint32_t*>(&h);
}
__device__ __forceinline__ void ldsm_x4(uint32_t& r0, uint32_t& r1, uint32_t& r2, uint32_t& r3,
                                        uint32_t addr) {
    asm volatile("ldmatrix.sync.aligned.m8n8.x4.shared.b16 {%0,%1,%2,%3}, [%4];"
                 : "=r"(r0), "=r"(r1), "=r"(r2), "=r"(r3) : "r"(addr));
}
__device__ __forceinline__ void mma_f16(float* d, const uint32_t* a, uint32_t b0, uint32_t b1) {
    asm volatile("mma.sync.aligned.m16n8k16.row.col.f32.f16.f16.f32 "
                 "{%0,%1,%2,%3}, {%4,%5,%6,%7}, {%8,%9}, {%0,%1,%2,%3};"
                 : "+f"(d[0]), "+f"(d[1]), "+f"(d[2]), "+f"(d[3])
                 : "r"(a[0]), "r"(a[1]), "r"(a[2]), "r"(a[3]), "r"(b0), "r"(b1));
}
__device__ __forceinline__ void cp16(uint32_t dst, const void* src) {
    asm volatile("cp.async.cg.shared.global [%0], [%1], 16;" :: "r"(dst), "l"(src));
}
__device__ __forceinline__ void prefetch_l2(const void* p) {
    asm volatile("prefetch.global.L2 [%0];" :: "l"(p));
}
#define CP_COMMIT() asm volatile("cp.async.commit_group;" ::: "memory")
#define CP_WAIT(n)  asm volatile("cp.async.wait_group %0;" :: "n"(n) : "memory")

// ---------------- device scratch ----------------
__device__ __align__(16) __nv_bfloat16 g_Xg[(size_t)N_NODES * HID];   // 64MB
__device__ __align__(16) __half g_W1T[HID * F_DIM];                   // [n][k] fp16
__device__ __align__(16) __half g_WgT[HID * HID];                     // [n][k] fp16
__device__ double g_sum_d, g_sumsq_d;
__device__ double g_pooled[HID];
__device__ float  g_h1[HID];
__device__ float  g_h2[POL];
__device__ float  g_h3[POL];

// ---------------------------------------------------------------------------
// single prep kernel: zero accumulators + convert both weights to fp16 [n][k]
__global__ void prep_kernel(const float* __restrict__ W1, const float* __restrict__ Wg) {
    int i = blockIdx.x * blockDim.x + threadIdx.x;
    if (i == 0) { g_sum_d = 0.0; g_sumsq_d = 0.0; }
    if (i < HID) g_pooled[i] = 0.0;
    if (i < HID * F_DIM) {                        // W1 is [128 k][256 n]
        int n = i >> 7, k = i & 127;
        g_W1T[i] = __float2half_rn(W1[k * HID + n]);
    }
    int j = i - HID * F_DIM;
    if (j >= 0 && j < HID * HID) {                // Wg is [256 k][256 n]
        int n = j >> 8, k = j & 255;
        g_WgT[j] = __float2half_rn(Wg[k * HID + n]);
    }
}

// ---------------------------------------------------------------------------
// stage one 64-k chunk of an fp16 weight array via cp.async.
// Buffer: [256 n][64 k] fp16, row pitch 144B.
__device__ __forceinline__ void stage_chunk(uint32_t sb, int tid, uint32_t off,
                                            const __half* __restrict__ src,
                                            int kpitch, int c) {
    #pragma unroll
    for (int i = tid; i < 2048; i += THREADS) {
        int n = i >> 3, q = i & 7;                // 8 x 16B per 64-k row
        uint32_t d = (uint32_t)(n * (SB_STR * 2) + q * 16);
        const char* s = (const char*)(src + (size_t)n * kpitch + c * 64) + q * 16;
        cp16(sb + off + d, s);
    }
    CP_COMMIT();
}

// ---------------------------------------------------------------------------
// Fused GEMM1+GEMM2 per 128-row tile; HMMA fp16, fp32 accumulate.
// 16 warps x (32x64) tiles; 64-k chunks double-buffered (6 iterations total).
__global__ __launch_bounds__(THREADS, 1)
void fused_gemm_kernel(const float* __restrict__ obs,
                       const float* __restrict__ b1, const float* __restrict__ bg)
{
    extern __shared__ char smem[];
    const uint32_t sb = smem_u32(smem);
    const int tid  = threadIdx.x;
    const int lane = tid & 31;
    const int wid  = tid >> 5;
    const int wm   = wid & 3;        // row group: 32 rows
    const int wn   = wid >> 2;       // col group: 64 cols
    const size_t row0 = (size_t)blockIdx.x * BM;

    const uint32_t b_off[2] = {OFF_B0, OFF_B1};

    // prefetch W1 chunk 0 -> buffer 0 (overlaps A staging below)
    stage_chunk(sb, tid, OFF_B0, g_W1T, F_DIM, 0);

    float* b1s = (float*)(smem + OFF_BB1);
    float* bgs = (float*)(smem + OFF_BBG);
    if (tid < 256) { b1s[tid] = b1[tid]; bgs[tid] = bg[tid]; }

    // ---- stage obs [128 x 128] fp32 -> fp16 into sA ----
    const float4* obs4 = reinterpret_cast<const float4*>(obs + row0 * F_DIM);
    #pragma unroll
    for (int i = tid; i < 128 * 32; i += THREADS) {
        int r = i >> 5, c4 = i & 31;
        float4 v = obs4[i];
        uint2 p = make_uint2(pack_h2(v.x, v.y), pack_h2(v.z, v.w));
        *(uint2*)(smem + OFF_A + r * (SA_STR * 2) + c4 * 8) = p;
    }

    float acc[16][4];
    #pragma unroll
    for (int t = 0; t < 16; ++t)
        #pragma unroll
        for (int j = 0; j < 4; ++j) acc[t][j] = 0.f;

    const int a_lrow = lane & 15;
    const int a_koff = (lane >> 4) << 3;
    const int b_noff = (lane & 7) + ((lane >> 4) << 3);
    const int b_koff = ((lane >> 3) & 1) << 3;

    // per-chunk compute: 4 k-steps of 16 over a 64-k chunk
    auto compute_chunk = [&](uint32_t a_off, uint32_t a_str2, int gk0, uint32_t bo) {
        #pragma unroll
        for (int ks = 0; ks < 4; ++ks) {
            int gk = gk0 + ks * 16;
            uint32_t af[2][4];
            #pragma unroll
            for (int mt = 0; mt < 2; ++mt) {
                uint32_t addr = sb + a_off
                    + (uint32_t)(wm * 32 + mt * 16 + a_lrow) * a_str2
                    + (uint32_t)(gk + a_koff) * 2;
                ldsm_x4(af[mt][0], af[mt][1], af[mt][2], af[mt][3], addr);
            }
            #pragma unroll
            for (int np = 0; np < 4; ++np) {
                uint32_t roff = (uint32_t)(wn * 64 + np * 16 + b_noff) * (SB_STR * 2)
                              + (uint32_t)(ks * 16 + b_koff) * 2;
                uint32_t r0, r1, r2, r3;
                ldsm_x4(r0, r1, r2, r3, sb + bo + roff);
                #pragma unroll
                for (int mt = 0; mt < 2; ++mt) {
                    mma_f16(acc[mt * 8 + np * 2],     af[mt], r0, r1);
                    mma_f16(acc[mt * 8 + np * 2 + 1], af[mt], r2, r3);
                }
            }
        }
    };

    // ---------------- GEMM1: K=128, 2 chunks of 64 ----------------
    for (int c = 0; c < 2; ++c) {
        int nb = (c + 1) & 1;
        if (c < 1) stage_chunk(sb, tid, b_off[nb], g_W1T, F_DIM, 1);
        else       stage_chunk(sb, tid, b_off[nb], g_WgT, HID, 0);
        CP_WAIT(1);
        __syncthreads();
        compute_chunk(OFF_A, SA_STR * 2, c * 64, b_off[c & 1]);
        __syncthreads();
    }

    // ---- epilogue 1: relu(acc + b1) -> fp16 sX, reset acc ----
    #pragma unroll
    for (int mt = 0; mt < 2; ++mt) {
        int rlo = wm * 32 + mt * 16 + (lane >> 2);
        #pragma unroll
        for (int nt = 0; nt < 8; ++nt) {
            int col = wn * 64 + nt * 8 + (lane & 3) * 2;
            float* a = acc[mt * 8 + nt];
            float v0 = fmaxf(a[0] + b1s[col],     0.f);
            float v1 = fmaxf(a[1] + b1s[col + 1], 0.f);
            float v2 = fmaxf(a[2] + b1s[col],     0.f);
            float v3 = fmaxf(a[3] + b1s[col + 1], 0.f);
            *(uint32_t*)(smem + OFF_X + rlo * (SX_STR * 2) + col * 2)       = pack_h2(v0, v1);
            *(uint32_t*)(smem + OFF_X + (rlo + 8) * (SX_STR * 2) + col * 2) = pack_h2(v2, v3);
            a[0] = a[1] = a[2] = a[3] = 0.f;
        }
    }

    // ---------------- GEMM2: K=256, 4 chunks (g = 2..5) ----------------
    for (int c = 0; c < 4; ++c) {
        int g = 2 + c;
        if (c < 3) {
            int nb = (g + 1) & 1;
            stage_chunk(sb, tid, b_off[nb], g_WgT, HID, c + 1);
            CP_WAIT(1);
        } else {
            CP_WAIT(0);
        }
        __syncthreads();
        compute_chunk(OFF_X, SX_STR * 2, c * 64, b_off[g & 1]);
        __syncthreads();
    }
    __syncthreads();   // everyone done reading sX before overwrite below

    // ---- epilogue 2: relu(acc + bg) -> bf16 into sX (overwrite) + stats ----
    float s_sum = 0.f, s_sq = 0.f;
    #pragma unroll
    for (int mt = 0; mt < 2; ++mt) {
        int rlo = wm * 32 + mt * 16 + (lane >> 2);
        #pragma unroll
        for (int nt = 0; nt < 8; ++nt) {
            int col = wn * 64 + nt * 8 + (lane & 3) * 2;
            float* a = acc[mt * 8 + nt];
            float v0 = fmaxf(a[0] + bgs[col],     0.f);
            float v1 = fmaxf(a[1] + bgs[col + 1], 0.f);
            float v2 = fmaxf(a[2] + bgs[col],     0.f);
            float v3 = fmaxf(a[3] + bgs[col + 1], 0.f);
            *(uint32_t*)(smem + OFF_X + rlo * (SX_STR * 2) + col * 2)       = pack_bf2(v0, v1);
            *(uint32_t*)(smem + OFF_X + (rlo + 8) * (SX_STR * 2) + col * 2) = pack_bf2(v2, v3);
            s_sum += (v0 + v1) + (v2 + v3);
            s_sq = fmaf(v0, v0, s_sq); s_sq = fmaf(v1, v1, s_sq);
            s_sq = fmaf(v2, v2, s_sq); s_sq = fmaf(v3, v3, s_sq);
        }
    }
    __syncthreads();

    // ---- coalesced copy sX -> g_Xg: 128 rows x 32 uint4 = 4096; 8 iters ----
    #pragma unroll
    for (int it = 0; it < 8; ++it) {
        int idx = tid + it * THREADS;
        int r = idx >> 5, q = idx & 31;
        uint4 v = *(uint4*)(smem + OFF_X + r * (SX_STR * 2) + q * 16);
        *(uint4*)((char*)g_Xg + (row0 + (size_t)r) * 512 + q * 16) = v;
    }

    // ---- block-reduce stats ----
    float* red = (float*)(smem + OFF_RED);
    red[tid] = s_sum; red[THREADS + tid] = s_sq;
    __syncthreads();
    for (int o = THREADS / 2; o > 0; o >>= 1) {
        if (tid < o) {
            red[tid] += red[tid + o];
            red[THREADS + tid] += red[THREADS + tid + o];
        }
        __syncthreads();
    }
    if (tid == 0) {
        atomicAdd(&g_sum_d,   (double)red[0]);
        atomicAdd(&g_sumsq_d, (double)red[THREADS]);
    }
}

// ---------------------------------------------------------------------------
// Gated pooling over bf16 Xg; finalize folded in. 512 blocks, 4-row ILP.
// Also warms the MLP weights (Wd/Wp1/Wp2, 1.75MB = 14336 lines) into L2 so
// the downstream gemvs hit L2 instead of cold DRAM.
__global__ __launch_bounds__(256)
void pool_kernel(const float* __restrict__ ln_w, const float* __restrict__ ln_b,
                 const float* __restrict__ Wgate, const float* __restrict__ bgate,
                 const float* __restrict__ Wd, const float* __restrict__ Wp1,
                 const float* __restrict__ Wp2)
{
    __shared__ float blk[HID];
    __shared__ float s_mu, s_inv;
    const int lane = threadIdx.x & 31;
    const int warp = (blockIdx.x * blockDim.x + threadIdx.x) >> 5;
    const int nwarps = (gridDim.x * blockDim.x) >> 5;   // 4096 warps

    // L2 warm for the MLP weights (one 128B line per early global thread)
    {
        int gt = blockIdx.x * blockDim.x + threadIdx.x;
        if (gt < 2048)        prefetch_l2(Wd  + (size_t)gt * 32);
        else if (gt < 6144)   prefetch_l2(Wp1 + (size_t)(gt - 2048) * 32);
        else if (gt < 14336)  prefetch_l2(Wp2 + (size_t)(gt - 6144) * 32);
    }

    for (int i = threadIdx.x; i < HID; i += blockDim.x) blk[i] = 0.f;
    if (threadIdx.x == 0) {
        double M = (double)N_NODES * (double)HID;
        double mu  = g_sum_d / M;
        double var = g_sumsq_d / M - mu * mu;
        if (var < 0.0) var = 0.0;
        s_mu  = (float)mu;
        s_inv = (float)(1.0 / (sqrt(var) + (double)LN_EPS));
    }
    __syncthreads();

    const float mu = s_mu, inv = s_inv;
    const int c0 = lane * 8;
    float lw[8], lb[8], wg[8], pp[8];
    #pragma unroll
    for (int j = 0; j < 8; ++j) {
        lw[j] = ln_w[c0 + j] * inv;
        lb[j] = ln_b[c0 + j];
        wg[j] = Wgate[c0 + j];
        pp[j] = 0.f;
    }
    const float bg0 = bgate[0];

    for (int r = warp * 4; r < N_NODES; r += nwarps * 4) {
        uint4 va[4];
        #pragma unroll
        for (int s = 0; s < 4; ++s)
            va[s] = *(const uint4*)((const char*)g_Xg + (size_t)(r + s) * 512 + c0 * 2);
        float x[4][8];
        #pragma unroll
        for (int s = 0; s < 4; ++s) {
            const uint32_t* pv = (const uint32_t*)&va[s];
            #pragma unroll
            for (int q = 0; q < 4; ++q) {
                float2 f = __bfloat1622float2(*(const __nv_bfloat162*)&pv[q]);
                x[s][2*q] = f.x; x[s][2*q+1] = f.y;
            }
        }
        float d[4] = {0.f, 0.f, 0.f, 0.f};
        #pragma unroll
        for (int s = 0; s < 4; ++s)
            #pragma unroll
            for (int j = 0; j < 8; ++j) {
                x[s][j] = fmaf(x[s][j] - mu, lw[j], lb[j]);
                d[s] = fmaf(x[s][j], wg[j], d[s]);
            }
        #pragma unroll
        for (int o = 16; o > 0; o >>= 1) {
            #pragma unroll
            for (int s = 0; s < 4; ++s)
                d[s] += __shfl_xor_sync(0xffffffffu, d[s], o);
        }
        float g[4];
        #pragma unroll
        for (int s = 0; s < 4; ++s)
            g[s] = 1.f / (1.f + __expf(-(d[s] + bg0)));
        #pragma unroll
        for (int s = 0; s < 4; ++s)
            #pragma unroll
            for (int j = 0; j < 8; ++j)
                pp[j] = fmaf(g[s], x[s][j], pp[j]);
    }
    #pragma unroll
    for (int j = 0; j < 8; ++j) atomicAdd(&blk[c0 + j], pp[j]);
    __syncthreads();
    for (int i = threadIdx.x; i < HID; i += blockDim.x)
        atomicAdd(&g_pooled[i], (double)blk[i]);
}

// ---------------------------------------------------------------------------
// GEMV layers, parallel across SMs. Block = 256 threads: 32 outputs x 8 k-slices.
// 4 rotating accumulators break the serial fmaf dependency chain.
template <int K, int N, bool IN_D>
__global__ __launch_bounds__(256)
void gemv_relu_kernel(const void* __restrict__ in_v, const float* __restrict__ W,
                      const float* __restrict__ b, float* __restrict__ out)
{
    __shared__ float sin[K];
    __shared__ float sred[256];
    const int tid = threadIdx.x;
    const int tx = tid & 31, ty = tid >> 5;
    const int n = blockIdx.x * 32 + tx;
    for (int i = tid; i < K; i += 256)
        sin[i] = IN_D ? (float)((const double*)in_v)[i] : ((const float*)in_v)[i];
    __syncthreads();
    float s0 = 0.f, s1 = 0.f, s2 = 0.f, s3 = 0.f;
    #pragma unroll
    for (int k = ty; k < K; k += 32) {
        s0 = fmaf(sin[k],      W[(size_t)k * N + n],        s0);
        s1 = fmaf(sin[k + 8],  W[(size_t)(k + 8) * N + n],  s1);
        s2 = fmaf(sin[k + 16], W[(size_t)(k + 16) * N + n], s2);
        s3 = fmaf(sin[k + 24], W[(size_t)(k + 24) * N + n], s3);
    }
    sred[tid] = (s0 + s1) + (s2 + s3);
    __syncthreads();
    #pragma unroll
    for (int o = 4; o > 0; o >>= 1) {
        if (ty < o) sred[tid] += sred[tid + o * 32];
        __syncthreads();
    }
    if (ty == 0) out[n] = fmaxf(sred[tx] + b[n], 0.f);
}

// ---------------------------------------------------------------------------
// value = h3 . Wv + bv (redundant per block, L2-resident) then out = value*mask.
__global__ __launch_bounds__(256)
void bcast_kernel(const float* __restrict__ Wv, const float* __restrict__ bv,
                  const float* __restrict__ mask, float* __restrict__ out)
{
    __shared__ float red[256];
    const int t = threadIdx.x;
    red[t] = g_h3[t] * Wv[t] + g_h3[t + 256] * Wv[t + 256];
    __syncthreads();
    #pragma unroll
    for (int o = 128; o > 0; o >>= 1) {
        if (t < o) red[t] += red[t + o];
        __syncthreads();
    }
    float value = red[0] + bv[0];
    int i = blockIdx.x * 256 + t;
    if (i < N_NODES) out[i] = value * mask[i];
}

// ---------------------------------------------------------------------------
extern "C" void kernel_launch(void* const* d_in, const int* in_sizes, int n_in,
                              void* d_out, int out_size)
{
    const float* obs   = (const float*)d_in[0];
    const float* mask  = (const float*)d_in[1];
    // d_in[2] = edge_index (self-loops only -> GCN == dense GEMM, see header)
    const float* W1    = (const float*)d_in[3];
    const float* b1    = (const float*)d_in[4];
    const float* Wg    = (const float*)d_in[5];
    const float* bg    = (const float*)d_in[6];
    const float* ln_w  = (const float*)d_in[7];
    const float* ln_b  = (const float*)d_in[8];
    const float* Wgate = (const float*)d_in[9];
    const float* bgate = (const float*)d_in[10];
    const float* Wd    = (const float*)d_in[11];
    const float* bd    = (const float*)d_in[12];
    const float* Wp1   = (const float*)d_in[13];
    const float* bp1   = (const float*)d_in[14];
    const float* Wp2   = (const float*)d_in[15];
    const float* bp2   = (const float*)d_in[16];
    const float* Wv    = (const float*)d_in[17];
    const float* bv    = (const float*)d_in[18];
    float* out = (float*)d_out;

    cudaFuncSetAttribute(fused_gemm_kernel,
                         cudaFuncAttributeMaxDynamicSharedMemorySize, SMEM_TOTAL);

    float* d_h1; cudaGetSymbolAddress((void**)&d_h1, g_h1);
    float* d_h2; cudaGetSymbolAddress((void**)&d_h2, g_h2);
    float* d_h3; cudaGetSymbolAddress((void**)&d_h3, g_h3);
    double* d_pooled; cudaGetSymbolAddress((void**)&d_pooled, g_pooled);

    prep_kernel<<<(HID * F_DIM + HID * HID + 255) / 256, 256>>>(W1, Wg);
    fused_gemm_kernel<<<N_NODES / BM, THREADS, SMEM_TOTAL>>>(obs, b1, bg);
    pool_kernel<<<512, 256>>>(ln_w, ln_b, Wgate, bgate, Wd, Wp1, Wp2);
    gemv_relu_kernel<HID, HID, true ><<<HID / 32, 256>>>(d_pooled, Wd,  bd,  d_h1);
    gemv_relu_kernel<HID, POL, false><<<POL / 32, 256>>>(d_h1,     Wp1, bp1, d_h2);
    gemv_relu_kernel<POL, POL, false><<<POL / 32, 256>>>(d_h2,     Wp2, bp2, d_h3);
    bcast_kernel<<<(N_NODES + 255) / 256, 256>>>(Wv, bv, mask, out);
}

// round 17
// speedup vs baseline: 1.2007x; 1.0174x over previous
#include <cuda_runtime.h>
#include <cuda_bf16.h>
#include <cuda_fp16.h>
#include <math.h>
#include <stdint.h>

// Graph_Critic_Model on GB300 (plain sm_103 target: no tcgen05; HMMA mma.sync path).
// Self-loop-only graph => GCNConv collapses to dense GEMM:
//   X  = relu(obs @ W1 + b1)   [131072,256]
//   Xg = relu(X @ Wg + bg)     [131072,256]
//   global LN over all elements; sigmoid-gated pooling; tiny MLP; broadcast.
// Precision (R12-proven): fp16 weights+activations, fp32 accumulate; Xg bf16.
// R17: pool 8-row ILP at fixed 512 blocks (doubles chip MLP, same atomic tail;
//      R14 showed adding blocks backfires). Everything else identical to R16.

#define N_NODES 131072
#define F_DIM   128
#define HID     256
#define POL     512
#define LN_EPS  1e-5f

#define BM      128         // rows per CTA
#define THREADS 512         // 16 warps: wm = wid&3 (32 rows), wn = wid>>2 (64 cols)

// smem strides (fp16 elems); pitches 272/144/528 bytes -> conflict-free ldmatrix
#define SA_STR 136
#define SB_STR 72           // 64-k weight chunk rows (144B pitch)
#define SX_STR 264

// smem byte offsets
#define OFF_A    0                    // 34816
#define OFF_B0   34816                // 36864 each buffer
#define OFF_B1   71680
#define OFF_X    108544               // 67584
#define OFF_BB1  176128               // 1024 (b1 floats)
#define OFF_BBG  177152               // 1024 (bg floats)
#define OFF_RED  178176               // 4096
#define SMEM_TOTAL 182272

// ---------------- helpers ----------------
__device__ __forceinline__ uint32_t smem_u32(const void* p) {
    uint32_t a;
    asm("{ .reg .u64 t; cvta.to.shared.u64 t, %1; cvt.u32.u64 %0, t; }" : "=r"(a) : "l"(p));
    return a;
}
__device__ __forceinline__ uint32_t pack_h2(float lo, float hi) {
    __half2 h = __floats2half2_rn(lo, hi);
    return *reinterpret_cast<uint32_t*>(&h);
}
__device__ __forceinline__ uint32_t pack_bf2(float lo, float hi) {
    __nv_bfloat162 h = __floats2bfloat162_rn(lo, hi);
    return *reinterpret_cast<uint32_t*>(&h);
}
__device__ __forceinline__ void ldsm_x4(uint32_t& r0, uint32_t& r1, uint32_t& r2, uint32_t& r3,
                                        uint32_t addr) {
    asm volatile("ldmatrix.sync.aligned.m8n8.x4.shared.b16 {%0,%1,%2,%3}, [%4];"
                 : "=r"(r0), "=r"(r1), "=r"(r2), "=r"(r3) : "r"(addr));
}
__device__ __forceinline__ void mma_f16(float* d, const uint32_t* a, uint32_t b0, uint32_t b1) {
    asm volatile("mma.sync.aligned.m16n8k16.row.col.f32.f16.f16.f32 "
                 "{%0,%1,%2,%3}, {%4,%5,%6,%7}, {%8,%9}, {%0,%1,%2,%3};"
                 : "+f"(d[0]), "+f"(d[1]), "+f"(d[2]), "+f"(d[3])
                 : "r"(a[0]), "r"(a[1]), "r"(a[2]), "r"(a[3]), "r"(b0), "r"(b1));
}
__device__ __forceinline__ void cp16(uint32_t dst, const void* src) {
    asm volatile("cp.async.cg.shared.global [%0], [%1], 16;" :: "r"(dst), "l"(src));
}
__device__ __forceinline__ void prefetch_l2(const void* p) {
    asm volatile("prefetch.global.L2 [%0];" :: "l"(p));
}
#define CP_COMMIT() asm volatile("cp.async.commit_group;" ::: "memory")
#define CP_WAIT(n)  asm volatile("cp.async.wait_group %0;" :: "n"(n) : "memory")

// ---------------- device scratch ----------------
__device__ __align__(16) __nv_bfloat16 g_Xg[(size_t)N_NODES * HID];   // 64MB
__device__ __align__(16) __half g_W1T[HID * F_DIM];                   // [n][k] fp16
__device__ __align__(16) __half g_WgT[HID * HID];                     // [n][k] fp16
__device__ double g_sum_d, g_sumsq_d;
__device__ double g_pooled[HID];
__device__ float  g_h1[HID];
__device__ float  g_h2[POL];
__device__ float  g_h3[POL];

// ---------------------------------------------------------------------------
// single prep kernel: zero accumulators + convert both weights to fp16 [n][k]
__global__ void prep_kernel(const float* __restrict__ W1, const float* __restrict__ Wg) {
    int i = blockIdx.x * blockDim.x + threadIdx.x;
    if (i == 0) { g_sum_d = 0.0; g_sumsq_d = 0.0; }
    if (i < HID) g_pooled[i] = 0.0;
    if (i < HID * F_DIM) {                        // W1 is [128 k][256 n]
        int n = i >> 7, k = i & 127;
        g_W1T[i] = __float2half_rn(W1[k * HID + n]);
    }
    int j = i - HID * F_DIM;
    if (j >= 0 && j < HID * HID) {                // Wg is [256 k][256 n]
        int n = j >> 8, k = j & 255;
        g_WgT[j] = __float2half_rn(Wg[k * HID + n]);
    }
}

// ---------------------------------------------------------------------------
// stage one 64-k chunk of an fp16 weight array via cp.async.
// Buffer: [256 n][64 k] fp16, row pitch 144B.
__device__ __forceinline__ void stage_chunk(uint32_t sb, int tid, uint32_t off,
                                            const __half* __restrict__ src,
                                            int kpitch, int c) {
    #pragma unroll
    for (int i = tid; i < 2048; i += THREADS) {
        int n = i >> 3, q = i & 7;                // 8 x 16B per 64-k row
        uint32_t d = (uint32_t)(n * (SB_STR * 2) + q * 16);
        const char* s = (const char*)(src + (size_t)n * kpitch + c * 64) + q * 16;
        cp16(sb + off + d, s);
    }
    CP_COMMIT();
}

// ---------------------------------------------------------------------------
// Fused GEMM1+GEMM2 per 128-row tile; HMMA fp16, fp32 accumulate.
// 16 warps x (32x64) tiles; 64-k chunks double-buffered (6 iterations total).
__global__ __launch_bounds__(THREADS, 1)
void fused_gemm_kernel(const float* __restrict__ obs,
                       const float* __restrict__ b1, const float* __restrict__ bg)
{
    extern __shared__ char smem[];
    const uint32_t sb = smem_u32(smem);
    const int tid  = threadIdx.x;
    const int lane = tid & 31;
    const int wid  = tid >> 5;
    const int wm   = wid & 3;        // row group: 32 rows
    const int wn   = wid >> 2;       // col group: 64 cols
    const size_t row0 = (size_t)blockIdx.x * BM;

    const uint32_t b_off[2] = {OFF_B0, OFF_B1};

    // prefetch W1 chunk 0 -> buffer 0 (overlaps A staging below)
    stage_chunk(sb, tid, OFF_B0, g_W1T, F_DIM, 0);

    float* b1s = (float*)(smem + OFF_BB1);
    float* bgs = (float*)(smem + OFF_BBG);
    if (tid < 256) { b1s[tid] = b1[tid]; bgs[tid] = bg[tid]; }

    // ---- stage obs [128 x 128] fp32 -> fp16 into sA ----
    const float4* obs4 = reinterpret_cast<const float4*>(obs + row0 * F_DIM);
    #pragma unroll
    for (int i = tid; i < 128 * 32; i += THREADS) {
        int r = i >> 5, c4 = i & 31;
        float4 v = obs4[i];
        uint2 p = make_uint2(pack_h2(v.x, v.y), pack_h2(v.z, v.w));
        *(uint2*)(smem + OFF_A + r * (SA_STR * 2) + c4 * 8) = p;
    }

    float acc[16][4];
    #pragma unroll
    for (int t = 0; t < 16; ++t)
        #pragma unroll
        for (int j = 0; j < 4; ++j) acc[t][j] = 0.f;

    const int a_lrow = lane & 15;
    const int a_koff = (lane >> 4) << 3;
    const int b_noff = (lane & 7) + ((lane >> 4) << 3);
    const int b_koff = ((lane >> 3) & 1) << 3;

    // per-chunk compute: 4 k-steps of 16 over a 64-k chunk
    auto compute_chunk = [&](uint32_t a_off, uint32_t a_str2, int gk0, uint32_t bo) {
        #pragma unroll
        for (int ks = 0; ks < 4; ++ks) {
            int gk = gk0 + ks * 16;
            uint32_t af[2][4];
            #pragma unroll
            for (int mt = 0; mt < 2; ++mt) {
                uint32_t addr = sb + a_off
                    + (uint32_t)(wm * 32 + mt * 16 + a_lrow) * a_str2
                    + (uint32_t)(gk + a_koff) * 2;
                ldsm_x4(af[mt][0], af[mt][1], af[mt][2], af[mt][3], addr);
            }
            #pragma unroll
            for (int np = 0; np < 4; ++np) {
                uint32_t roff = (uint32_t)(wn * 64 + np * 16 + b_noff) * (SB_STR * 2)
                              + (uint32_t)(ks * 16 + b_koff) * 2;
                uint32_t r0, r1, r2, r3;
                ldsm_x4(r0, r1, r2, r3, sb + bo + roff);
                #pragma unroll
                for (int mt = 0; mt < 2; ++mt) {
                    mma_f16(acc[mt * 8 + np * 2],     af[mt], r0, r1);
                    mma_f16(acc[mt * 8 + np * 2 + 1], af[mt], r2, r3);
                }
            }
        }
    };

    // ---------------- GEMM1: K=128, 2 chunks of 64 ----------------
    for (int c = 0; c < 2; ++c) {
        int nb = (c + 1) & 1;
        if (c < 1) stage_chunk(sb, tid, b_off[nb], g_W1T, F_DIM, 1);
        else       stage_chunk(sb, tid, b_off[nb], g_WgT, HID, 0);
        CP_WAIT(1);
        __syncthreads();
        compute_chunk(OFF_A, SA_STR * 2, c * 64, b_off[c & 1]);
        __syncthreads();
    }

    // ---- epilogue 1: relu(acc + b1) -> fp16 sX, reset acc ----
    #pragma unroll
    for (int mt = 0; mt < 2; ++mt) {
        int rlo = wm * 32 + mt * 16 + (lane >> 2);
        #pragma unroll
        for (int nt = 0; nt < 8; ++nt) {
            int col = wn * 64 + nt * 8 + (lane & 3) * 2;
            float* a = acc[mt * 8 + nt];
            float v0 = fmaxf(a[0] + b1s[col],     0.f);
            float v1 = fmaxf(a[1] + b1s[col + 1], 0.f);
            float v2 = fmaxf(a[2] + b1s[col],     0.f);
            float v3 = fmaxf(a[3] + b1s[col + 1], 0.f);
            *(uint32_t*)(smem + OFF_X + rlo * (SX_STR * 2) + col * 2)       = pack_h2(v0, v1);
            *(uint32_t*)(smem + OFF_X + (rlo + 8) * (SX_STR * 2) + col * 2) = pack_h2(v2, v3);
            a[0] = a[1] = a[2] = a[3] = 0.f;
        }
    }

    // ---------------- GEMM2: K=256, 4 chunks (g = 2..5) ----------------
    for (int c = 0; c < 4; ++c) {
        int g = 2 + c;
        if (c < 3) {
            int nb = (g + 1) & 1;
            stage_chunk(sb, tid, b_off[nb], g_WgT, HID, c + 1);
            CP_WAIT(1);
        } else {
            CP_WAIT(0);
        }
        __syncthreads();
        compute_chunk(OFF_X, SX_STR * 2, c * 64, b_off[g & 1]);
        __syncthreads();
    }
    __syncthreads();   // everyone done reading sX before overwrite below

    // ---- epilogue 2: relu(acc + bg) -> bf16 into sX (overwrite) + stats ----
    float s_sum = 0.f, s_sq = 0.f;
    #pragma unroll
    for (int mt = 0; mt < 2; ++mt) {
        int rlo = wm * 32 + mt * 16 + (lane >> 2);
        #pragma unroll
        for (int nt = 0; nt < 8; ++nt) {
            int col = wn * 64 + nt * 8 + (lane & 3) * 2;
            float* a = acc[mt * 8 + nt];
            float v0 = fmaxf(a[0] + bgs[col],     0.f);
            float v1 = fmaxf(a[1] + bgs[col + 1], 0.f);
            float v2 = fmaxf(a[2] + bgs[col],     0.f);
            float v3 = fmaxf(a[3] + bgs[col + 1], 0.f);
            *(uint32_t*)(smem + OFF_X + rlo * (SX_STR * 2) + col * 2)       = pack_bf2(v0, v1);
            *(uint32_t*)(smem + OFF_X + (rlo + 8) * (SX_STR * 2) + col * 2) = pack_bf2(v2, v3);
            s_sum += (v0 + v1) + (v2 + v3);
            s_sq = fmaf(v0, v0, s_sq); s_sq = fmaf(v1, v1, s_sq);
            s_sq = fmaf(v2, v2, s_sq); s_sq = fmaf(v3, v3, s_sq);
        }
    }
    __syncthreads();

    // ---- coalesced copy sX -> g_Xg: 128 rows x 32 uint4 = 4096; 8 iters ----
    #pragma unroll
    for (int it = 0; it < 8; ++it) {
        int idx = tid + it * THREADS;
        int r = idx >> 5, q = idx & 31;
        uint4 v = *(uint4*)(smem + OFF_X + r * (SX_STR * 2) + q * 16);
        *(uint4*)((char*)g_Xg + (row0 + (size_t)r) * 512 + q * 16) = v;
    }

    // ---- block-reduce stats ----
    float* red = (float*)(smem + OFF_RED);
    red[tid] = s_sum; red[THREADS + tid] = s_sq;
    __syncthreads();
    for (int o = THREADS / 2; o > 0; o >>= 1) {
        if (tid < o) {
            red[tid] += red[tid + o];
            red[THREADS + tid] += red[THREADS + tid + o];
        }
        __syncthreads();
    }
    if (tid == 0) {
        atomicAdd(&g_sum_d,   (double)red[0]);
        atomicAdd(&g_sumsq_d, (double)red[THREADS]);
    }
}

// ---------------------------------------------------------------------------
// Gated pooling over bf16 Xg; finalize folded in. 512 blocks, 8-row ILP
// (double chip-wide MLP at the same atomic-tail cost).
// Also warms the MLP weights (Wd/Wp1/Wp2, 1.75MB) into L2 for the gemvs.
__global__ __launch_bounds__(256)
void pool_kernel(const float* __restrict__ ln_w, const float* __restrict__ ln_b,
                 const float* __restrict__ Wgate, const float* __restrict__ bgate,
                 const float* __restrict__ Wd, const float* __restrict__ Wp1,
                 const float* __restrict__ Wp2)
{
    __shared__ float blk[HID];
    __shared__ float s_mu, s_inv;
    const int lane = threadIdx.x & 31;
    const int warp = (blockIdx.x * blockDim.x + threadIdx.x) >> 5;
    const int nwarps = (gridDim.x * blockDim.x) >> 5;   // 4096 warps

    // L2 warm for the MLP weights (one 128B line per early global thread)
    {
        int gt = blockIdx.x * blockDim.x + threadIdx.x;
        if (gt < 2048)        prefetch_l2(Wd  + (size_t)gt * 32);
        else if (gt < 6144)   prefetch_l2(Wp1 + (size_t)(gt - 2048) * 32);
        else if (gt < 14336)  prefetch_l2(Wp2 + (size_t)(gt - 6144) * 32);
    }

    for (int i = threadIdx.x; i < HID; i += blockDim.x) blk[i] = 0.f;
    if (threadIdx.x == 0) {
        double M = (double)N_NODES * (double)HID;
        double mu  = g_sum_d / M;
        double var = g_sumsq_d / M - mu * mu;
        if (var < 0.0) var = 0.0;
        s_mu  = (float)mu;
        s_inv = (float)(1.0 / (sqrt(var) + (double)LN_EPS));
    }
    __syncthreads();

    const float mu = s_mu, inv = s_inv;
    const int c0 = lane * 8;
    float lw[8], lb[8], wg[8], pp[8];
    #pragma unroll
    for (int j = 0; j < 8; ++j) {
        lw[j] = ln_w[c0 + j] * inv;
        lb[j] = ln_b[c0 + j];
        wg[j] = Wgate[c0 + j];
        pp[j] = 0.f;
    }
    const float bg0 = bgate[0];

    // 131072 rows / (4096 warps * 8 rows) = 4 iterations
    for (int r = warp * 8; r < N_NODES; r += nwarps * 8) {
        uint4 va[8];
        #pragma unroll
        for (int s = 0; s < 8; ++s)
            va[s] = *(const uint4*)((const char*)g_Xg + (size_t)(r + s) * 512 + c0 * 2);
        float d[8];
        float x[8][8];
        #pragma unroll
        for (int s = 0; s < 8; ++s) {
            const uint32_t* pv = (const uint32_t*)&va[s];
            d[s] = 0.f;
            #pragma unroll
            for (int q = 0; q < 4; ++q) {
                float2 f = __bfloat1622float2(*(const __nv_bfloat162*)&pv[q]);
                x[s][2*q]   = fmaf(f.x - mu, lw[2*q],   lb[2*q]);
                x[s][2*q+1] = fmaf(f.y - mu, lw[2*q+1], lb[2*q+1]);
                d[s] = fmaf(x[s][2*q],   wg[2*q],   d[s]);
                d[s] = fmaf(x[s][2*q+1], wg[2*q+1], d[s]);
            }
        }
        #pragma unroll
        for (int o = 16; o > 0; o >>= 1) {
            #pragma unroll
            for (int s = 0; s < 8; ++s)
                d[s] += __shfl_xor_sync(0xffffffffu, d[s], o);
        }
        #pragma unroll
        for (int s = 0; s < 8; ++s) {
            float g = 1.f / (1.f + __expf(-(d[s] + bg0)));
            #pragma unroll
            for (int j = 0; j < 8; ++j)
                pp[j] = fmaf(g, x[s][j], pp[j]);
        }
    }
    #pragma unroll
    for (int j = 0; j < 8; ++j) atomicAdd(&blk[c0 + j], pp[j]);
    __syncthreads();
    for (int i = threadIdx.x; i < HID; i += blockDim.x)
        atomicAdd(&g_pooled[i], (double)blk[i]);
}

// ---------------------------------------------------------------------------
// GEMV layers, parallel across SMs. Block = 256 threads: 32 outputs x 8 k-slices.
// 4 rotating accumulators break the serial fmaf dependency chain.
template <int K, int N, bool IN_D>
__global__ __launch_bounds__(256)
void gemv_relu_kernel(const void* __restrict__ in_v, const float* __restrict__ W,
                      const float* __restrict__ b, float* __restrict__ out)
{
    __shared__ float sin[K];
    __shared__ float sred[256];
    const int tid = threadIdx.x;
    const int tx = tid & 31, ty = tid >> 5;
    const int n = blockIdx.x * 32 + tx;
    for (int i = tid; i < K; i += 256)
        sin[i] = IN_D ? (float)((const double*)in_v)[i] : ((const float*)in_v)[i];
    __syncthreads();
    float s0 = 0.f, s1 = 0.f, s2 = 0.f, s3 = 0.f;
    #pragma unroll
    for (int k = ty; k < K; k += 32) {
        s0 = fmaf(sin[k],      W[(size_t)k * N + n],        s0);
        s1 = fmaf(sin[k + 8],  W[(size_t)(k + 8) * N + n],  s1);
        s2 = fmaf(sin[k + 16], W[(size_t)(k + 16) * N + n], s2);
        s3 = fmaf(sin[k + 24], W[(size_t)(k + 24) * N + n], s3);
    }
    sred[tid] = (s0 + s1) + (s2 + s3);
    __syncthreads();
    #pragma unroll
    for (int o = 4; o > 0; o >>= 1) {
        if (ty < o) sred[tid] += sred[tid + o * 32];
        __syncthreads();
    }
    if (ty == 0) out[n] = fmaxf(sred[tx] + b[n], 0.f);
}

// ---------------------------------------------------------------------------
// value = h3 . Wv + bv (redundant per block, L2-resident) then out = value*mask.
__global__ __launch_bounds__(256)
void bcast_kernel(const float* __restrict__ Wv, const float* __restrict__ bv,
                  const float* __restrict__ mask, float* __restrict__ out)
{
    __shared__ float red[256];
    const int t = threadIdx.x;
    red[t] = g_h3[t] * Wv[t] + g_h3[t + 256] * Wv[t + 256];
    __syncthreads();
    #pragma unroll
    for (int o = 128; o > 0; o >>= 1) {
        if (t < o) red[t] += red[t + o];
        __syncthreads();
    }
    float value = red[0] + bv[0];
    int i = blockIdx.x * 256 + t;
    if (i < N_NODES) out[i] = value * mask[i];
}

// ---------------------------------------------------------------------------
extern "C" void kernel_launch(void* const* d_in, const int* in_sizes, int n_in,
                              void* d_out, int out_size)
{
    const float* obs   = (const float*)d_in[0];
    const float* mask  = (const float*)d_in[1];
    // d_in[2] = edge_index (self-loops only -> GCN == dense GEMM, see header)
    const float* W1    = (const float*)d_in[3];
    const float* b1    = (const float*)d_in[4];
    const float* Wg    = (const float*)d_in[5];
    const float* bg    = (const float*)d_in[6];
    const float* ln_w  = (const float*)d_in[7];
    const float* ln_b  = (const float*)d_in[8];
    const float* Wgate = (const float*)d_in[9];
    const float* bgate = (const float*)d_in[10];
    const float* Wd    = (const float*)d_in[11];
    const float* bd    = (const float*)d_in[12];
    const float* Wp1   = (const float*)d_in[13];
    const float* bp1   = (const float*)d_in[14];
    const float* Wp2   = (const float*)d_in[15];
    const float* bp2   = (const float*)d_in[16];
    const float* Wv    = (const float*)d_in[17];
    const float* bv    = (const float*)d_in[18];
    float* out = (float*)d_out;

    cudaFuncSetAttribute(fused_gemm_kernel,
                         cudaFuncAttributeMaxDynamicSharedMemorySize, SMEM_TOTAL);

    float* d_h1; cudaGetSymbolAddress((void**)&d_h1, g_h1);
    float* d_h2; cudaGetSymbolAddress((void**)&d_h2, g_h2);
    float* d_h3; cudaGetSymbolAddress((void**)&d_h3, g_h3);
    double* d_pooled; cudaGetSymbolAddress((void**)&d_pooled, g_pooled);

    prep_kernel<<<(HID * F_DIM + HID * HID + 255) / 256, 256>>>(W1, Wg);
    fused_gemm_kernel<<<N_NODES / BM, THREADS, SMEM_TOTAL>>>(obs, b1, bg);
    pool_kernel<<<512, 256>>>(ln_w, ln_b, Wgate, bgate, Wd, Wp1, Wp2);
    gemv_relu_kernel<HID, HID, true ><<<HID / 32, 256>>>(d_pooled, Wd,  bd,  d_h1);
    gemv_relu_kernel<HID, POL, false><<<POL / 32, 256>>>(d_h1,     Wp1, bp1, d_h2);
    gemv_relu_kernel<POL, POL, false><<<POL / 32, 256>>>(d_h2,     Wp2, bp2, d_h3);
    bcast_kernel<<<(N_NODES + 255) / 256, 256>>>(Wv, bv, mask, out);
}